// round 3
// baseline (speedup 1.0000x reference)
#include <cuda_runtime.h>
#include <cuda_bf16.h>
#include <cstdint>

// Problem constants (fixed by setup_inputs)
#define BATCH 2
#define LSEQ  2048
#define DMODEL 1024
#define NHEADS 16
#define DH 64
#define ROWS (BATCH * LSEQ)          // 4096
#define QKVC (3 * DMODEL)            // 3072
#define QT   64                      // queries per attention CTA
#define KT   192                     // keys per attention CTA (64 + 128)

typedef unsigned long long ull;

// ---------------------------------------------------------------------------
// f32x2 packed helpers (sm_100a): 2 fp32 FMAs per issue slot
// ---------------------------------------------------------------------------
__device__ __forceinline__ ull pk2(float lo, float hi) {
    ull r;
    asm("mov.b64 %0, {%1, %2};" : "=l"(r) : "f"(lo), "f"(hi));
    return r;
}
__device__ __forceinline__ void upk2(ull v, float& lo, float& hi) {
    asm("mov.b64 {%0, %1}, %2;" : "=f"(lo), "=f"(hi) : "l"(v));
}
__device__ __forceinline__ void ffma2(ull& d, ull a, ull b) {
    asm("fma.rn.f32x2 %0, %1, %2, %0;" : "+l"(d) : "l"(a), "l"(b));
}

// ---------------------------------------------------------------------------
// Scratch (device globals; no allocation at runtime)
// ---------------------------------------------------------------------------
__device__ float g_xn [ROWS * DMODEL];   // 16 MB
__device__ float g_qkv[ROWS * QKVC];     // 48 MB
__device__ float g_att[ROWS * DMODEL];   // 16 MB

// ---------------------------------------------------------------------------
// RMSNorm: one block per row (4096 rows), 256 threads, float4 path
// ---------------------------------------------------------------------------
__global__ __launch_bounds__(256) void rmsnorm_kernel(
    const float* __restrict__ x, const float* __restrict__ w,
    float* __restrict__ out)
{
    const int row = blockIdx.x;
    const float4* xr = reinterpret_cast<const float4*>(x + (size_t)row * DMODEL);
    float4 v = xr[threadIdx.x];          // 256 threads * 4 = 1024 elems
    float ss = v.x*v.x + v.y*v.y + v.z*v.z + v.w*v.w;

    #pragma unroll
    for (int o = 16; o > 0; o >>= 1)
        ss += __shfl_xor_sync(0xffffffffu, ss, o);

    __shared__ float red[8];
    const int wid = threadIdx.x >> 5, lane = threadIdx.x & 31;
    if (lane == 0) red[wid] = ss;
    __syncthreads();
    if (wid == 0) {
        float t = (lane < 8) ? red[lane] : 0.0f;
        #pragma unroll
        for (int o = 4; o > 0; o >>= 1)
            t += __shfl_xor_sync(0xffffffffu, t, o);
        if (lane == 0) red[0] = rsqrtf(t * (1.0f / DMODEL) + 1e-6f);
    }
    __syncthreads();
    const float s = red[0];
    float4 wv = reinterpret_cast<const float4*>(w)[threadIdx.x];
    float4 o4 = make_float4(v.x*s*wv.x, v.y*s*wv.y, v.z*s*wv.z, v.w*s*wv.w);
    reinterpret_cast<float4*>(out + (size_t)row * DMODEL)[threadIdx.x] = o4;
}

// ---------------------------------------------------------------------------
// SGEMM (NT): C[m,n] = sum_k A[m,k] * B[n,k] (+ skip[m,n])
// 128x128 tile, BK=16, double-buffered smem, 256 threads, 8x8 microtile,
// inner product via packed fma.rn.f32x2 (acc paired along n).
// All M,N,K here are multiples of the tile dims (no bounds checks).
// ---------------------------------------------------------------------------
template <bool ADD_SKIP>
__global__ __launch_bounds__(256, 2) void sgemm_nt(
    const float* __restrict__ A, const float* __restrict__ B,
    const float* __restrict__ skip, float* __restrict__ C,
    int M, int N, int K)
{
    __shared__ float As[2][16][128];   // [stage][k][m]
    __shared__ float Bs[2][16][128];   // [stage][k][n]

    const int tid  = threadIdx.x;
    const int tr   = tid >> 4;            // 0..15 (microtile row)
    const int tc   = tid & 15;            // 0..15 (microtile col)
    const int row0 = blockIdx.y * 128;
    const int col0 = blockIdx.x * 128;

    // global->smem mapping: thread loads 8 consecutive k of one row
    const int ar = tid & 127;             // row within tile
    const int ac = (tid >> 7) << 3;       // k-offset: 0 or 8
    const float* Ap = A + (size_t)(row0 + ar) * K + ac;
    const float* Bp = B + (size_t)(col0 + ar) * K + ac;

    ull acc2[8][4];
    #pragma unroll
    for (int i = 0; i < 8; i++)
        #pragma unroll
        for (int j = 0; j < 4; j++) acc2[i][j] = 0ULL;

    float4 pa0, pa1, pb0, pb1;

    // prologue: stage 0
    pa0 = *reinterpret_cast<const float4*>(Ap);
    pa1 = *reinterpret_cast<const float4*>(Ap + 4);
    pb0 = *reinterpret_cast<const float4*>(Bp);
    pb1 = *reinterpret_cast<const float4*>(Bp + 4);
    {
        As[0][ac+0][ar]=pa0.x; As[0][ac+1][ar]=pa0.y; As[0][ac+2][ar]=pa0.z; As[0][ac+3][ar]=pa0.w;
        As[0][ac+4][ar]=pa1.x; As[0][ac+5][ar]=pa1.y; As[0][ac+6][ar]=pa1.z; As[0][ac+7][ar]=pa1.w;
        Bs[0][ac+0][ar]=pb0.x; Bs[0][ac+1][ar]=pb0.y; Bs[0][ac+2][ar]=pb0.z; Bs[0][ac+3][ar]=pb0.w;
        Bs[0][ac+4][ar]=pb1.x; Bs[0][ac+5][ar]=pb1.y; Bs[0][ac+6][ar]=pb1.z; Bs[0][ac+7][ar]=pb1.w;
    }
    __syncthreads();

    const int nsteps = K >> 4;            // 64 for K=1024
    int buf = 0;
    for (int ks = 0; ks < nsteps; ks++) {
        // prefetch next stage into registers (hides global latency)
        if (ks + 1 < nsteps) {
            const int ko = (ks + 1) << 4;
            pa0 = *reinterpret_cast<const float4*>(Ap + ko);
            pa1 = *reinterpret_cast<const float4*>(Ap + ko + 4);
            pb0 = *reinterpret_cast<const float4*>(Bp + ko);
            pb1 = *reinterpret_cast<const float4*>(Bp + ko + 4);
        }

        // compute on current stage
        #pragma unroll
        for (int kk = 0; kk < 16; kk++) {
            float4 a0 = *reinterpret_cast<const float4*>(&As[buf][kk][tr*8]);
            float4 a1 = *reinterpret_cast<const float4*>(&As[buf][kk][tr*8+4]);
            float4 b0 = *reinterpret_cast<const float4*>(&Bs[buf][kk][tc*8]);
            float4 b1 = *reinterpret_cast<const float4*>(&Bs[buf][kk][tc*8+4]);
            ull bp[4];
            bp[0] = pk2(b0.x, b0.y); bp[1] = pk2(b0.z, b0.w);
            bp[2] = pk2(b1.x, b1.y); bp[3] = pk2(b1.z, b1.w);
            float av[8] = {a0.x,a0.y,a0.z,a0.w,a1.x,a1.y,a1.z,a1.w};
            #pragma unroll
            for (int i = 0; i < 8; i++) {
                ull ad = pk2(av[i], av[i]);
                #pragma unroll
                for (int j = 0; j < 4; j++)
                    ffma2(acc2[i][j], ad, bp[j]);
            }
        }

        // store prefetched stage, flip
        if (ks + 1 < nsteps) {
            const int nb = buf ^ 1;
            As[nb][ac+0][ar]=pa0.x; As[nb][ac+1][ar]=pa0.y; As[nb][ac+2][ar]=pa0.z; As[nb][ac+3][ar]=pa0.w;
            As[nb][ac+4][ar]=pa1.x; As[nb][ac+5][ar]=pa1.y; As[nb][ac+6][ar]=pa1.z; As[nb][ac+7][ar]=pa1.w;
            Bs[nb][ac+0][ar]=pb0.x; Bs[nb][ac+1][ar]=pb0.y; Bs[nb][ac+2][ar]=pb0.z; Bs[nb][ac+3][ar]=pb0.w;
            Bs[nb][ac+4][ar]=pb1.x; Bs[nb][ac+5][ar]=pb1.y; Bs[nb][ac+6][ar]=pb1.z; Bs[nb][ac+7][ar]=pb1.w;
            __syncthreads();
            buf = nb;
        }
    }

    // epilogue
    #pragma unroll
    for (int i = 0; i < 8; i++) {
        const size_t off = (size_t)(row0 + tr*8 + i) * N + col0 + tc*8;
        float c[8];
        upk2(acc2[i][0], c[0], c[1]);
        upk2(acc2[i][1], c[2], c[3]);
        upk2(acc2[i][2], c[4], c[5]);
        upk2(acc2[i][3], c[6], c[7]);
        float4 c0 = make_float4(c[0], c[1], c[2], c[3]);
        float4 c1 = make_float4(c[4], c[5], c[6], c[7]);
        if (ADD_SKIP) {
            float4 s0 = *reinterpret_cast<const float4*>(skip + off);
            float4 s1 = *reinterpret_cast<const float4*>(skip + off + 4);
            c0.x += s0.x; c0.y += s0.y; c0.z += s0.z; c0.w += s0.w;
            c1.x += s1.x; c1.y += s1.y; c1.z += s1.z; c1.w += s1.w;
        }
        *reinterpret_cast<float4*>(C + off)     = c0;
        *reinterpret_cast<float4*>(C + off + 4) = c1;
    }
}

// ---------------------------------------------------------------------------
// Banded attention. Grid: (L/QT, H, B), 256 threads.
// Each CTA: 64 queries of one (b,h). Keys j=0..191 map to kglob = q0-64+j.
// 4 threads per query (part = tid&3); each owns 48 keys.
// K tile staged in 48 KB static smem; V streamed from global.
// Hot loops use packed f32x2 FMA.
// ---------------------------------------------------------------------------
__global__ __launch_bounds__(256) void attn_kernel(
    const float* __restrict__ qkv, float* __restrict__ att)
{
    __shared__ float Ks[KT * DH];        // exactly 48 KB

    const int qt = blockIdx.x, h = blockIdx.y, b = blockIdx.z;
    const int q0 = qt * QT;
    const int k0 = q0 - 64;
    const int tid  = threadIdx.x;
    const int part = tid & 3;
    const int q    = tid >> 2;           // 0..63
    const size_t base = (size_t)b * LSEQ * QKVC;

    // cooperative K-tile load (zero-fill out-of-range rows)
    for (int idx = tid; idx < KT * (DH/4); idx += 256) {
        const int j = idx >> 4, dc = idx & 15;
        const int kg = k0 + j;
        float4 val = make_float4(0.f, 0.f, 0.f, 0.f);
        if (kg >= 0 && kg < LSEQ)
            val = *reinterpret_cast<const float4*>(
                qkv + base + (size_t)kg * QKVC + DMODEL + h*DH + dc*4);
        *reinterpret_cast<float4*>(&Ks[j*DH + dc*4]) = val;
    }
    __syncthreads();

    // q row into packed pairs (4 threads share the row; L1 broadcast)
    ull q2[DH/2];
    {
        const float4* qp = reinterpret_cast<const float4*>(
            qkv + base + (size_t)(q0 + q) * QKVC + h*DH);
        #pragma unroll
        for (int dc = 0; dc < 16; dc++) {
            float4 v = qp[dc];
            q2[dc*2+0] = pk2(v.x, v.y);
            q2[dc*2+1] = pk2(v.z, v.w);
        }
    }

    // scores for this thread's 48 keys (packed dot product)
    float p[48];
    float mx = -1e30f;
    #pragma unroll
    for (int jj = 0; jj < 48; jj++) {
        const int j = part * 48 + jj;
        ull s2 = 0ULL;
        const float4* kp = reinterpret_cast<const float4*>(&Ks[j*DH]);
        #pragma unroll
        for (int dc = 0; dc < 16; dc++) {
            float4 kv = kp[dc];
            ffma2(s2, q2[dc*2+0], pk2(kv.x, kv.y));
            ffma2(s2, q2[dc*2+1], pk2(kv.z, kv.w));
        }
        float lo, hi;
        upk2(s2, lo, hi);
        float s = (lo + hi) * 0.125f;    // 1/sqrt(64)
        const int kg = k0 + j;
        const bool valid = (j >= q) && (j <= q + 128) && (kg >= 0) && (kg < LSEQ);
        s = valid ? s : -1e30f;
        p[jj] = s;
        mx = fmaxf(mx, s);
    }
    // row max / sum across the 4 partner lanes (lanes differ in bits 0..1)
    mx = fmaxf(mx, __shfl_xor_sync(0xffffffffu, mx, 1));
    mx = fmaxf(mx, __shfl_xor_sync(0xffffffffu, mx, 2));
    float sum = 0.0f;
    #pragma unroll
    for (int jj = 0; jj < 48; jj++) {
        const float e = __expf(p[jj] - mx);   // masked entries underflow to 0
        p[jj] = e;
        sum += e;
    }
    sum += __shfl_xor_sync(0xffffffffu, sum, 1);
    sum += __shfl_xor_sync(0xffffffffu, sum, 2);
    const float inv = 1.0f / sum;             // self-key always valid => sum > 0

    // P @ V (V streamed from global; clamped address + p==0 kills OOB rows)
    ull acc2[DH/2];
    #pragma unroll
    for (int d = 0; d < DH/2; d++) acc2[d] = 0ULL;
    #pragma unroll
    for (int jj = 0; jj < 48; jj++) {
        const float pv = p[jj] * inv;
        const ull pv2 = pk2(pv, pv);
        int kg = k0 + part * 48 + jj;
        kg = (kg < 0) ? 0 : ((kg >= LSEQ) ? (LSEQ - 1) : kg);
        const float4* vp = reinterpret_cast<const float4*>(
            qkv + base + (size_t)kg * QKVC + 2*DMODEL + h*DH);
        #pragma unroll
        for (int dc = 0; dc < 16; dc++) {
            float4 v = vp[dc];
            ffma2(acc2[dc*2+0], pv2, pk2(v.x, v.y));
            ffma2(acc2[dc*2+1], pv2, pk2(v.z, v.w));
        }
    }
    // reduce partials across the 4 partner lanes and write
    float acc[DH];
    #pragma unroll
    for (int d = 0; d < DH/2; d++)
        upk2(acc2[d], acc[d*2], acc[d*2+1]);
    #pragma unroll
    for (int d = 0; d < DH; d++) {
        float r = acc[d];
        r += __shfl_xor_sync(0xffffffffu, r, 1);
        r += __shfl_xor_sync(0xffffffffu, r, 2);
        acc[d] = r;
    }
    if (part == 0) {
        float* orow = att + ((size_t)b * LSEQ + q0 + q) * DMODEL + h*DH;
        #pragma unroll
        for (int dc = 0; dc < 16; dc++)
            *reinterpret_cast<float4*>(&orow[dc*4]) =
                make_float4(acc[dc*4+0], acc[dc*4+1], acc[dc*4+2], acc[dc*4+3]);
    }
}

// ---------------------------------------------------------------------------
// Launch
// ---------------------------------------------------------------------------
extern "C" void kernel_launch(void* const* d_in, const int* in_sizes, int n_in,
                              void* d_out, int out_size)
{
    const float* x      = (const float*)d_in[0];
    const float* w_norm = (const float*)d_in[1];
    const float* w_qkv  = (const float*)d_in[2];
    const float* w_out  = (const float*)d_in[3];
    float* out = (float*)d_out;

    float *xn_p, *qkv_p, *att_p;
    cudaGetSymbolAddress((void**)&xn_p,  g_xn);
    cudaGetSymbolAddress((void**)&qkv_p, g_qkv);
    cudaGetSymbolAddress((void**)&att_p, g_att);

    // 1) RMSNorm
    rmsnorm_kernel<<<ROWS, 256>>>(x, w_norm, xn_p);

    // 2) QKV = xn @ w_qkv^T : [4096,3072]
    {
        dim3 grid(QKVC / 128, ROWS / 128);   // (24, 32)
        sgemm_nt<false><<<grid, 256>>>(xn_p, w_qkv, nullptr, qkv_p,
                                       ROWS, QKVC, DMODEL);
    }

    // 3) Banded attention
    {
        dim3 grid(LSEQ / QT, NHEADS, BATCH); // (32, 16, 2)
        attn_kernel<<<grid, 256>>>(qkv_p, att_p);
    }

    // 4) out = att @ w_out^T + x : [4096,1024]
    {
        dim3 grid(DMODEL / 128, ROWS / 128); // (8, 32)
        sgemm_nt<true><<<grid, 256>>>(att_p, w_out, x, out,
                                      ROWS, DMODEL, DMODEL);
    }
}

// round 5
// speedup vs baseline: 1.5110x; 1.5110x over previous
#include <cuda_runtime.h>
#include <cuda_bf16.h>
#include <cstdint>

// Problem constants (fixed by setup_inputs)
#define BATCH 2
#define LSEQ  2048
#define DMODEL 1024
#define NHEADS 16
#define DH 64
#define ROWS (BATCH * LSEQ)          // 4096
#define QKVC (3 * DMODEL)            // 3072
#define QT   64                      // queries per attention CTA
#define KT   192                     // keys per attention CTA (64 + 128)

#define K3   (3 * DMODEL)            // bf16-split concatenated K = 3072
#define BK   32                      // bf16 k per smem tile
#define NKT3 (K3 / BK)               // 96 k-tiles
#define SMROW 80                     // padded smem row bytes (64B data + 16B pad)

// ---------------------------------------------------------------------------
// Scratch (device globals; no allocation at runtime)
// ---------------------------------------------------------------------------
__device__ float          g_qkv   [ROWS * QKVC];     // fp32 qkv (48 MB)
__device__ __nv_bfloat16  g_xnb   [ROWS * K3];       // xn split [hi|hi|lo]
__device__ __nv_bfloat16  g_attb  [ROWS * K3];       // att split [hi|hi|lo]
__device__ __nv_bfloat16  g_wqkvb [QKVC * K3];       // w_qkv split [hi|lo|hi]
__device__ __nv_bfloat16  g_woutb [DMODEL * K3];     // w_out split [hi|lo|hi]

// ---------------------------------------------------------------------------
// Baseline-ISA helpers (sm_80-class only: cp.async, ldmatrix, mma.sync)
// ---------------------------------------------------------------------------
__device__ __forceinline__ uint32_t smem_u32(const void* p) {
    uint32_t a;
    asm("{ .reg .u64 t; cvta.to.shared.u64 t, %1; cvt.u32.u64 %0, t; }"
        : "=r"(a) : "l"(p));
    return a;
}
__device__ __forceinline__ void cp16(uint32_t s, const void* g) {
    asm volatile("cp.async.cg.shared.global [%0], [%1], 16;"
                 :: "r"(s), "l"(g) : "memory");
}
#define CP_COMMIT() asm volatile("cp.async.commit_group;" ::: "memory")
#define CP_WAIT(n)  asm volatile("cp.async.wait_group %0;" :: "n"(n) : "memory")

__device__ __forceinline__ void ldmx4(uint32_t* r, uint32_t addr) {
    asm volatile("ldmatrix.sync.aligned.m8n8.x4.shared.b16 {%0,%1,%2,%3}, [%4];"
                 : "=r"(r[0]), "=r"(r[1]), "=r"(r[2]), "=r"(r[3]) : "r"(addr));
}
__device__ __forceinline__ void mma16816(float* d, const uint32_t* a,
                                         uint32_t b0, uint32_t b1) {
    asm volatile(
        "mma.sync.aligned.m16n8k16.row.col.f32.bf16.bf16.f32 "
        "{%0,%1,%2,%3}, {%4,%5,%6,%7}, {%8,%9}, {%0,%1,%2,%3};"
        : "+f"(d[0]), "+f"(d[1]), "+f"(d[2]), "+f"(d[3])
        : "r"(a[0]), "r"(a[1]), "r"(a[2]), "r"(a[3]), "r"(b0), "r"(b1));
}

// ---------------------------------------------------------------------------
// RMSNorm fused with bf16 split: writes [hi|hi|lo] activation layout
// ---------------------------------------------------------------------------
__global__ __launch_bounds__(256) void rmsnorm_split_kernel(
    const float* __restrict__ x, const float* __restrict__ w,
    __nv_bfloat16* __restrict__ xb)
{
    const int row = blockIdx.x;
    const float4* xr = reinterpret_cast<const float4*>(x + (size_t)row * DMODEL);
    float4 v = xr[threadIdx.x];
    float ss = v.x*v.x + v.y*v.y + v.z*v.z + v.w*v.w;

    #pragma unroll
    for (int o = 16; o > 0; o >>= 1)
        ss += __shfl_xor_sync(0xffffffffu, ss, o);

    __shared__ float red[8];
    const int wid = threadIdx.x >> 5, lane = threadIdx.x & 31;
    if (lane == 0) red[wid] = ss;
    __syncthreads();
    if (wid == 0) {
        float t = (lane < 8) ? red[lane] : 0.0f;
        #pragma unroll
        for (int o = 4; o > 0; o >>= 1)
            t += __shfl_xor_sync(0xffffffffu, t, o);
        if (lane == 0) red[0] = rsqrtf(t * (1.0f / DMODEL) + 1e-6f);
    }
    __syncthreads();
    const float s = red[0];
    float4 wv = reinterpret_cast<const float4*>(w)[threadIdx.x];
    float o4[4] = { v.x*s*wv.x, v.y*s*wv.y, v.z*s*wv.z, v.w*s*wv.w };

    __nv_bfloat16 h[4], l[4];
    #pragma unroll
    for (int i = 0; i < 4; i++) {
        h[i] = __float2bfloat16(o4[i]);
        l[i] = __float2bfloat16(o4[i] - __bfloat162float(h[i]));
    }
    __nv_bfloat16* rowb = xb + (size_t)row * K3;
    const int c = threadIdx.x * 4;
    *reinterpret_cast<uint2*>(&rowb[c])              = *reinterpret_cast<uint2*>(h);
    *reinterpret_cast<uint2*>(&rowb[DMODEL + c])     = *reinterpret_cast<uint2*>(h);
    *reinterpret_cast<uint2*>(&rowb[2*DMODEL + c])   = *reinterpret_cast<uint2*>(l);
}

// ---------------------------------------------------------------------------
// Weight split: [hi|lo|hi] layout
// ---------------------------------------------------------------------------
__global__ __launch_bounds__(256) void split_w_kernel(
    const float* __restrict__ W, __nv_bfloat16* __restrict__ Wb, int total)
{
    int i = blockIdx.x * blockDim.x + threadIdx.x;
    if (i >= total) return;
    const int r = i >> 10, c = i & 1023;
    float x = W[i];
    __nv_bfloat16 h = __float2bfloat16(x);
    __nv_bfloat16 l = __float2bfloat16(x - __bfloat162float(h));
    __nv_bfloat16* row = Wb + (size_t)r * K3;
    row[c]              = h;
    row[DMODEL + c]     = l;
    row[2*DMODEL + c]   = h;
}

// ---------------------------------------------------------------------------
// bf16 HMMA GEMM (NT over split-K3): C[m,n] = sum_k3 A[m,k3]*B[n,k3] (+skip)
// 128x128 CTA tile, BK=32, cp.async double-buffer, 8 warps (warp tile 64x32),
// mma.sync.m16n8k16 bf16 -> fp32. 80B-padded smem rows (conflict-free ldmatrix).
// ---------------------------------------------------------------------------
template <bool ADD_SKIP>
__global__ __launch_bounds__(256) void gemm_bf16_mma(
    const __nv_bfloat16* __restrict__ A, const __nv_bfloat16* __restrict__ B,
    const float* __restrict__ skip, float* __restrict__ C, int N)
{
    __shared__ __align__(16) char smA[2][128 * SMROW];   // 20 KB
    __shared__ __align__(16) char smB[2][128 * SMROW];   // 20 KB

    const int tid  = threadIdx.x;
    const int warp = tid >> 5, lane = tid & 31;
    const int row0 = blockIdx.y * 128;
    const int col0 = blockIdx.x * 128;
    const int wm = (warp >> 2) * 64;    // 0 or 64
    const int wn = (warp & 3) * 32;     // 0,32,64,96

    const uint32_t sA = smem_u32(smA);
    const uint32_t sB = smem_u32(smB);

    // loader: 512 16B-chunks per matrix per tile; 2 per thread
    const int c0 = tid, c1 = tid + 256;
    const int r0c = c0 >> 2, k0c = (c0 & 3);
    const int r1c = c1 >> 2, k1c = (c1 & 3);
    const __nv_bfloat16* Ag0 = A + (size_t)(row0 + r0c) * K3 + k0c * 8;
    const __nv_bfloat16* Ag1 = A + (size_t)(row0 + r1c) * K3 + k1c * 8;
    const __nv_bfloat16* Bg0 = B + (size_t)(col0 + r0c) * K3 + k0c * 8;
    const __nv_bfloat16* Bg1 = B + (size_t)(col0 + r1c) * K3 + k1c * 8;
    const uint32_t stA0 = sA + r0c * SMROW + k0c * 16;
    const uint32_t stA1 = sA + r1c * SMROW + k1c * 16;
    const uint32_t stB0 = sB + r0c * SMROW + k0c * 16;
    const uint32_t stB1 = sB + r1c * SMROW + k1c * 16;

    float acc[4][4][4];
    #pragma unroll
    for (int i = 0; i < 4; i++)
        #pragma unroll
        for (int j = 0; j < 4; j++)
            #pragma unroll
            for (int f = 0; f < 4; f++) acc[i][j][f] = 0.0f;

    // ldmatrix per-lane address components
    const int arow = lane & 15;                       // A: row within m16
    const int asel = (lane >> 4) * 16;                // A: 0 or 16 bytes (k half)
    const int brow = (lane & 7) + ((lane >> 4) << 3); // B: n within n16
    const int bsel = ((lane >> 3) & 1) * 16;          // B: k half bytes

    // stage 0
    cp16(stA0, Ag0); cp16(stA1, Ag1);
    cp16(stB0, Bg0); cp16(stB1, Bg1);
    CP_COMMIT();

    for (int kt = 0; kt < NKT3; kt++) {
        const uint32_t stg = (uint32_t)(kt & 1) * (128 * SMROW);
        if (kt + 1 < NKT3) {
            const uint32_t nst = (uint32_t)((kt + 1) & 1) * (128 * SMROW);
            const int ko = (kt + 1) * BK;
            cp16(stA0 + nst, Ag0 + ko); cp16(stA1 + nst, Ag1 + ko);
            cp16(stB0 + nst, Bg0 + ko); cp16(stB1 + nst, Bg1 + ko);
            CP_COMMIT();
            CP_WAIT(1);
        } else {
            CP_WAIT(0);
        }
        __syncthreads();

        #pragma unroll
        for (int s = 0; s < 2; s++) {          // two k16 steps per BK=32
            uint32_t afr[4][4];
            #pragma unroll
            for (int mt = 0; mt < 4; mt++)
                ldmx4(afr[mt], sA + stg + (uint32_t)((wm + mt*16 + arow) * SMROW
                                                     + s*32 + asel));
            uint32_t bfr[2][4];
            #pragma unroll
            for (int nq = 0; nq < 2; nq++)
                ldmx4(bfr[nq], sB + stg + (uint32_t)((wn + nq*16 + brow) * SMROW
                                                     + s*32 + bsel));
            #pragma unroll
            for (int mt = 0; mt < 4; mt++)
                #pragma unroll
                for (int nt = 0; nt < 4; nt++)
                    mma16816(acc[mt][nt], afr[mt],
                             bfr[nt >> 1][(nt & 1) * 2],
                             bfr[nt >> 1][(nt & 1) * 2 + 1]);
        }
        __syncthreads();
    }

    // epilogue: frag layout m16n8: (c0,c1)->row g, cols 2t,2t+1; (c2,c3)->row g+8
    const int er = lane >> 2, ec = (lane & 3) * 2;
    #pragma unroll
    for (int mt = 0; mt < 4; mt++) {
        #pragma unroll
        for (int nt = 0; nt < 4; nt++) {
            const int gr = row0 + wm + mt*16 + er;
            const int gc = col0 + wn + nt*8 + ec;
            float2 v0 = make_float2(acc[mt][nt][0], acc[mt][nt][1]);
            float2 v1 = make_float2(acc[mt][nt][2], acc[mt][nt][3]);
            if (ADD_SKIP) {
                float2 s0 = *reinterpret_cast<const float2*>(skip + (size_t)gr * N + gc);
                float2 s1 = *reinterpret_cast<const float2*>(skip + (size_t)(gr+8) * N + gc);
                v0.x += s0.x; v0.y += s0.y; v1.x += s1.x; v1.y += s1.y;
            }
            *reinterpret_cast<float2*>(C + (size_t)gr * N + gc)     = v0;
            *reinterpret_cast<float2*>(C + (size_t)(gr+8) * N + gc) = v1;
        }
    }
}

// ---------------------------------------------------------------------------
// Banded attention. Grid: (L/QT, H, B), 256 threads. 4 threads/query, 48 keys.
// Phase 1: K tile in 48KB smem -> scores+softmax (regs).
// Phase 2: REUSE the same smem buffer for the V tile -> PV from smem
//          (kills the 3MB/CTA global V streaming of earlier rounds).
// Epilogue writes bf16-split att [hi|hi|lo].
// ---------------------------------------------------------------------------
__global__ __launch_bounds__(256) void attn_kernel(
    const float* __restrict__ qkv, __nv_bfloat16* __restrict__ attb)
{
    __shared__ float Ks[KT * DH];        // 48 KB, reused for V in phase 2

    const int qt = blockIdx.x, h = blockIdx.y, b = blockIdx.z;
    const int q0 = qt * QT;
    const int k0 = q0 - 64;
    const int tid  = threadIdx.x;
    const int part = tid & 3;
    const int q    = tid >> 2;
    const size_t base = (size_t)b * LSEQ * QKVC;

    // ---- phase 1: K tile ----
    for (int idx = tid; idx < KT * (DH/4); idx += 256) {
        const int j = idx >> 4, dc = idx & 15;
        const int kg = k0 + j;
        float4 val = make_float4(0.f, 0.f, 0.f, 0.f);
        if (kg >= 0 && kg < LSEQ)
            val = *reinterpret_cast<const float4*>(
                qkv + base + (size_t)kg * QKVC + DMODEL + h*DH + dc*4);
        *reinterpret_cast<float4*>(&Ks[j*DH + dc*4]) = val;
    }
    __syncthreads();

    float qf[DH];
    {
        const float4* qp = reinterpret_cast<const float4*>(
            qkv + base + (size_t)(q0 + q) * QKVC + h*DH);
        #pragma unroll
        for (int dc = 0; dc < 16; dc++) {
            float4 v = qp[dc];
            qf[dc*4+0] = v.x; qf[dc*4+1] = v.y; qf[dc*4+2] = v.z; qf[dc*4+3] = v.w;
        }
    }

    float p[48];
    float mx = -1e30f;
    #pragma unroll
    for (int jj = 0; jj < 48; jj++) {
        const int j = part * 48 + jj;
        float s = 0.0f;
        const float4* kp = reinterpret_cast<const float4*>(&Ks[j*DH]);
        #pragma unroll
        for (int dc = 0; dc < 16; dc++) {
            float4 kv = kp[dc];
            s += qf[dc*4+0]*kv.x + qf[dc*4+1]*kv.y
               + qf[dc*4+2]*kv.z + qf[dc*4+3]*kv.w;
        }
        s *= 0.125f;
        const int kg = k0 + j;
        const bool valid = (j >= q) && (j <= q + 128) && (kg >= 0) && (kg < LSEQ);
        s = valid ? s : -1e30f;
        p[jj] = s;
        mx = fmaxf(mx, s);
    }
    mx = fmaxf(mx, __shfl_xor_sync(0xffffffffu, mx, 1));
    mx = fmaxf(mx, __shfl_xor_sync(0xffffffffu, mx, 2));
    float sum = 0.0f;
    #pragma unroll
    for (int jj = 0; jj < 48; jj++) {
        const float e = __expf(p[jj] - mx);
        p[jj] = e;
        sum += e;
    }
    sum += __shfl_xor_sync(0xffffffffu, sum, 1);
    sum += __shfl_xor_sync(0xffffffffu, sum, 2);
    const float inv = 1.0f / sum;

    // ---- phase 2: V tile into the SAME smem buffer ----
    __syncthreads();     // all reads of K done
    for (int idx = tid; idx < KT * (DH/4); idx += 256) {
        const int j = idx >> 4, dc = idx & 15;
        const int kg = k0 + j;
        float4 val = make_float4(0.f, 0.f, 0.f, 0.f);
        if (kg >= 0 && kg < LSEQ)
            val = *reinterpret_cast<const float4*>(
                qkv + base + (size_t)kg * QKVC + 2*DMODEL + h*DH + dc*4);
        *reinterpret_cast<float4*>(&Ks[j*DH + dc*4]) = val;
    }
    __syncthreads();

    float acc[DH];
    #pragma unroll
    for (int d = 0; d < DH; d++) acc[d] = 0.0f;
    #pragma unroll
    for (int jj = 0; jj < 48; jj++) {
        const float pv = p[jj] * inv;    // 0 outside band/sequence
        const int j = part * 48 + jj;
        const float4* vp = reinterpret_cast<const float4*>(&Ks[j*DH]);
        #pragma unroll
        for (int dc = 0; dc < 16; dc++) {
            float4 v = vp[dc];
            acc[dc*4+0] += pv * v.x; acc[dc*4+1] += pv * v.y;
            acc[dc*4+2] += pv * v.z; acc[dc*4+3] += pv * v.w;
        }
    }
    #pragma unroll
    for (int d = 0; d < DH; d++) {
        float r = acc[d];
        r += __shfl_xor_sync(0xffffffffu, r, 1);
        r += __shfl_xor_sync(0xffffffffu, r, 2);
        acc[d] = r;
    }
    if (part == 0) {
        __nv_bfloat16* rowb = attb + ((size_t)b * LSEQ + q0 + q) * K3;
        #pragma unroll
        for (int dc = 0; dc < 16; dc++) {
            __nv_bfloat16 hh[4], ll[4];
            #pragma unroll
            for (int i = 0; i < 4; i++) {
                const float v = acc[dc*4+i];
                hh[i] = __float2bfloat16(v);
                ll[i] = __float2bfloat16(v - __bfloat162float(hh[i]));
            }
            const int c = h*DH + dc*4;
            *reinterpret_cast<uint2*>(&rowb[c])            = *reinterpret_cast<uint2*>(hh);
            *reinterpret_cast<uint2*>(&rowb[DMODEL + c])   = *reinterpret_cast<uint2*>(hh);
            *reinterpret_cast<uint2*>(&rowb[2*DMODEL + c]) = *reinterpret_cast<uint2*>(ll);
        }
    }
}

// ---------------------------------------------------------------------------
// Launch
// ---------------------------------------------------------------------------
extern "C" void kernel_launch(void* const* d_in, const int* in_sizes, int n_in,
                              void* d_out, int out_size)
{
    const float* x      = (const float*)d_in[0];
    const float* w_norm = (const float*)d_in[1];
    const float* w_qkv  = (const float*)d_in[2];
    const float* w_out  = (const float*)d_in[3];
    float* out = (float*)d_out;

    float *qkv_p;
    __nv_bfloat16 *xnb_p, *attb_p, *wqkvb_p, *woutb_p;
    cudaGetSymbolAddress((void**)&qkv_p,   g_qkv);
    cudaGetSymbolAddress((void**)&xnb_p,   g_xnb);
    cudaGetSymbolAddress((void**)&attb_p,  g_attb);
    cudaGetSymbolAddress((void**)&wqkvb_p, g_wqkvb);
    cudaGetSymbolAddress((void**)&woutb_p, g_woutb);

    // 1) RMSNorm + bf16 split of activations
    rmsnorm_split_kernel<<<ROWS, 256>>>(x, w_norm, xnb_p);

    // 1b) weight splits
    split_w_kernel<<<(QKVC * DMODEL + 255) / 256, 256>>>(w_qkv, wqkvb_p, QKVC * DMODEL);
    split_w_kernel<<<(DMODEL * DMODEL + 255) / 256, 256>>>(w_out, woutb_p, DMODEL * DMODEL);

    // 2) QKV GEMM (HMMA): [4096,3072] fp32
    {
        dim3 grid(QKVC / 128, ROWS / 128);   // (24, 32)
        gemm_bf16_mma<false><<<grid, 256>>>(xnb_p, wqkvb_p, nullptr, qkv_p, QKVC);
    }

    // 3) Banded attention (fp32), writes bf16-split att
    {
        dim3 grid(LSEQ / QT, NHEADS, BATCH); // (32, 16, 2)
        attn_kernel<<<grid, 256>>>(qkv_p, attb_p);
    }

    // 4) out GEMM (HMMA) + skip: [4096,1024] fp32
    {
        dim3 grid(DMODEL / 128, ROWS / 128); // (8, 32)
        gemm_bf16_mma<true><<<grid, 256>>>(attb_p, woutb_p, x, out, DMODEL);
    }
}

// round 6
// speedup vs baseline: 1.5340x; 1.0153x over previous
#include <cuda_runtime.h>
#include <cuda_bf16.h>
#include <cstdint>

// Problem constants (fixed by setup_inputs)
#define BATCH 2
#define LSEQ  2048
#define DMODEL 1024
#define NHEADS 16
#define DH 64
#define ROWS (BATCH * LSEQ)          // 4096
#define QKVC (3 * DMODEL)            // 3072
#define QT   64                      // queries per attention CTA
#define KT   192                     // keys per attention CTA (64 + 128)
#define PROW 196                     // padded Ps row (floats) -> 2-way conflicts max

#define K3   (3 * DMODEL)            // bf16-split concatenated K = 3072
#define BK   32                      // bf16 k per smem tile
#define NKT3 (K3 / BK)               // 96 k-tiles
#define SMROW 80                     // padded smem row bytes (64B data + 16B pad)
#define STAGE_BYTES (128 * SMROW)    // 10240 B per matrix per stage
#define GEMM_SMEM (3 * 2 * STAGE_BYTES)          // 61440 B
#define ATTN_SMEM ((KT * DH + QT * PROW) * 4)    // 99328 B

// ---------------------------------------------------------------------------
// Scratch (device globals; no allocation at runtime)
// ---------------------------------------------------------------------------
__device__ float          g_qkv   [ROWS * QKVC];     // fp32 qkv (48 MB)
__device__ __nv_bfloat16  g_xnb   [ROWS * K3];       // xn split [hi|hi|lo]
__device__ __nv_bfloat16  g_attb  [ROWS * K3];       // att split [hi|hi|lo]
__device__ __nv_bfloat16  g_wqkvb [QKVC * K3];       // w_qkv split [hi|lo|hi]
__device__ __nv_bfloat16  g_woutb [DMODEL * K3];     // w_out split [hi|lo|hi]

// ---------------------------------------------------------------------------
// Baseline-ISA helpers (sm_80-class only: cp.async, ldmatrix, mma.sync)
// ---------------------------------------------------------------------------
__device__ __forceinline__ uint32_t smem_u32(const void* p) {
    uint32_t a;
    asm("{ .reg .u64 t; cvta.to.shared.u64 t, %1; cvt.u32.u64 %0, t; }"
        : "=r"(a) : "l"(p));
    return a;
}
__device__ __forceinline__ void cp16(uint32_t s, const void* g) {
    asm volatile("cp.async.cg.shared.global [%0], [%1], 16;"
                 :: "r"(s), "l"(g) : "memory");
}
#define CP_COMMIT() asm volatile("cp.async.commit_group;" ::: "memory")
#define CP_WAIT(n)  asm volatile("cp.async.wait_group %0;" :: "n"(n) : "memory")

__device__ __forceinline__ void ldmx4(uint32_t* r, uint32_t addr) {
    asm volatile("ldmatrix.sync.aligned.m8n8.x4.shared.b16 {%0,%1,%2,%3}, [%4];"
                 : "=r"(r[0]), "=r"(r[1]), "=r"(r[2]), "=r"(r[3]) : "r"(addr));
}
__device__ __forceinline__ void mma16816(float* d, const uint32_t* a,
                                         uint32_t b0, uint32_t b1) {
    asm volatile(
        "mma.sync.aligned.m16n8k16.row.col.f32.bf16.bf16.f32 "
        "{%0,%1,%2,%3}, {%4,%5,%6,%7}, {%8,%9}, {%0,%1,%2,%3};"
        : "+f"(d[0]), "+f"(d[1]), "+f"(d[2]), "+f"(d[3])
        : "r"(a[0]), "r"(a[1]), "r"(a[2]), "r"(a[3]), "r"(b0), "r"(b1));
}

// ---------------------------------------------------------------------------
// RMSNorm fused with bf16 split: writes [hi|hi|lo] activation layout
// ---------------------------------------------------------------------------
__global__ __launch_bounds__(256) void rmsnorm_split_kernel(
    const float* __restrict__ x, const float* __restrict__ w,
    __nv_bfloat16* __restrict__ xb)
{
    const int row = blockIdx.x;
    const float4* xr = reinterpret_cast<const float4*>(x + (size_t)row * DMODEL);
    float4 v = xr[threadIdx.x];
    float ss = v.x*v.x + v.y*v.y + v.z*v.z + v.w*v.w;

    #pragma unroll
    for (int o = 16; o > 0; o >>= 1)
        ss += __shfl_xor_sync(0xffffffffu, ss, o);

    __shared__ float red[8];
    const int wid = threadIdx.x >> 5, lane = threadIdx.x & 31;
    if (lane == 0) red[wid] = ss;
    __syncthreads();
    if (wid == 0) {
        float t = (lane < 8) ? red[lane] : 0.0f;
        #pragma unroll
        for (int o = 4; o > 0; o >>= 1)
            t += __shfl_xor_sync(0xffffffffu, t, o);
        if (lane == 0) red[0] = rsqrtf(t * (1.0f / DMODEL) + 1e-6f);
    }
    __syncthreads();
    const float s = red[0];
    float4 wv = reinterpret_cast<const float4*>(w)[threadIdx.x];
    float o4[4] = { v.x*s*wv.x, v.y*s*wv.y, v.z*s*wv.z, v.w*s*wv.w };

    __nv_bfloat16 h[4], l[4];
    #pragma unroll
    for (int i = 0; i < 4; i++) {
        h[i] = __float2bfloat16(o4[i]);
        l[i] = __float2bfloat16(o4[i] - __bfloat162float(h[i]));
    }
    __nv_bfloat16* rowb = xb + (size_t)row * K3;
    const int c = threadIdx.x * 4;
    *reinterpret_cast<uint2*>(&rowb[c])              = *reinterpret_cast<uint2*>(h);
    *reinterpret_cast<uint2*>(&rowb[DMODEL + c])     = *reinterpret_cast<uint2*>(h);
    *reinterpret_cast<uint2*>(&rowb[2*DMODEL + c])   = *reinterpret_cast<uint2*>(l);
}

// ---------------------------------------------------------------------------
// Weight split: [hi|lo|hi] layout
// ---------------------------------------------------------------------------
__global__ __launch_bounds__(256) void split_w_kernel(
    const float* __restrict__ W, __nv_bfloat16* __restrict__ Wb, int total)
{
    int i = blockIdx.x * blockDim.x + threadIdx.x;
    if (i >= total) return;
    const int r = i >> 10, c = i & 1023;
    float x = W[i];
    __nv_bfloat16 h = __float2bfloat16(x);
    __nv_bfloat16 l = __float2bfloat16(x - __bfloat162float(h));
    __nv_bfloat16* row = Wb + (size_t)r * K3;
    row[c]              = h;
    row[DMODEL + c]     = l;
    row[2*DMODEL + c]   = h;
}

// ---------------------------------------------------------------------------
// bf16 HMMA GEMM (NT over split-K3): C[m,n] = sum_k3 A[m,k3]*B[n,k3] (+skip)
// 128x128 CTA tile, BK=32, 3-stage cp.async pipeline (dynamic smem),
// 8 warps (warp tile 64x32), mma.sync.m16n8k16 bf16 -> fp32.
// ---------------------------------------------------------------------------
template <bool ADD_SKIP>
__global__ __launch_bounds__(256, 2) void gemm_bf16_mma(
    const __nv_bfloat16* __restrict__ A, const __nv_bfloat16* __restrict__ B,
    const float* __restrict__ skip, float* __restrict__ C, int N)
{
    extern __shared__ __align__(16) char dynsm[];

    const int tid  = threadIdx.x;
    const int warp = tid >> 5, lane = tid & 31;
    const int row0 = blockIdx.y * 128;
    const int col0 = blockIdx.x * 128;
    const int wm = (warp >> 2) * 64;    // 0 or 64
    const int wn = (warp & 3) * 32;     // 0,32,64,96

    const uint32_t sA = smem_u32(dynsm);                     // 3 stages A
    const uint32_t sB = sA + 3 * STAGE_BYTES;                // 3 stages B

    // loader: 512 16B-chunks per matrix per tile; 2 per thread
    const int c0 = tid, c1 = tid + 256;
    const int r0c = c0 >> 2, k0c = (c0 & 3);
    const int r1c = c1 >> 2, k1c = (c1 & 3);
    const __nv_bfloat16* Ag0 = A + (size_t)(row0 + r0c) * K3 + k0c * 8;
    const __nv_bfloat16* Ag1 = A + (size_t)(row0 + r1c) * K3 + k1c * 8;
    const __nv_bfloat16* Bg0 = B + (size_t)(col0 + r0c) * K3 + k0c * 8;
    const __nv_bfloat16* Bg1 = B + (size_t)(col0 + r1c) * K3 + k1c * 8;
    const uint32_t stA0 = sA + r0c * SMROW + k0c * 16;
    const uint32_t stA1 = sA + r1c * SMROW + k1c * 16;
    const uint32_t stB0 = sB + r0c * SMROW + k0c * 16;
    const uint32_t stB1 = sB + r1c * SMROW + k1c * 16;

    float acc[4][4][4];
    #pragma unroll
    for (int i = 0; i < 4; i++)
        #pragma unroll
        for (int j = 0; j < 4; j++)
            #pragma unroll
            for (int f = 0; f < 4; f++) acc[i][j][f] = 0.0f;

    // ldmatrix per-lane address components
    const int arow = lane & 15;                       // A: row within m16
    const int asel = (lane >> 4) * 16;                // A: 0 or 16 bytes (k half)
    const int brow = (lane & 7) + ((lane >> 4) << 3); // B: n within n16
    const int bsel = ((lane >> 3) & 1) * 16;          // B: k half bytes

    // prologue: stages 0,1
    #pragma unroll
    for (int st = 0; st < 2; st++) {
        const uint32_t so = (uint32_t)st * STAGE_BYTES;
        const int ko = st * BK;
        cp16(stA0 + so, Ag0 + ko); cp16(stA1 + so, Ag1 + ko);
        cp16(stB0 + so, Bg0 + ko); cp16(stB1 + so, Bg1 + ko);
        CP_COMMIT();
    }

    int stg = 0;
    for (int kt = 0; kt < NKT3; kt++) {
        if (kt + 2 < NKT3) {
            const uint32_t so = (uint32_t)((kt + 2) % 3) * STAGE_BYTES;
            const int ko = (kt + 2) * BK;
            cp16(stA0 + so, Ag0 + ko); cp16(stA1 + so, Ag1 + ko);
            cp16(stB0 + so, Bg0 + ko); cp16(stB1 + so, Bg1 + ko);
            CP_COMMIT();
            CP_WAIT(2);
        } else if (kt + 1 < NKT3) {
            CP_WAIT(1);
        } else {
            CP_WAIT(0);
        }
        __syncthreads();

        const uint32_t so = (uint32_t)stg * STAGE_BYTES;
        #pragma unroll
        for (int s = 0; s < 2; s++) {          // two k16 steps per BK=32
            uint32_t afr[4][4];
            #pragma unroll
            for (int mt = 0; mt < 4; mt++)
                ldmx4(afr[mt], sA + so + (uint32_t)((wm + mt*16 + arow) * SMROW
                                                    + s*32 + asel));
            uint32_t bfr[2][4];
            #pragma unroll
            for (int nq = 0; nq < 2; nq++)
                ldmx4(bfr[nq], sB + so + (uint32_t)((wn + nq*16 + brow) * SMROW
                                                    + s*32 + bsel));
            #pragma unroll
            for (int mt = 0; mt < 4; mt++)
                #pragma unroll
                for (int nt = 0; nt < 4; nt++)
                    mma16816(acc[mt][nt], afr[mt],
                             bfr[nt >> 1][(nt & 1) * 2],
                             bfr[nt >> 1][(nt & 1) * 2 + 1]);
        }
        __syncthreads();
        stg = (stg + 1) % 3;
    }

    // epilogue: frag layout m16n8: (c0,c1)->row g, cols 2t,2t+1; (c2,c3)->row g+8
    const int er = lane >> 2, ec = (lane & 3) * 2;
    #pragma unroll
    for (int mt = 0; mt < 4; mt++) {
        #pragma unroll
        for (int nt = 0; nt < 4; nt++) {
            const int gr = row0 + wm + mt*16 + er;
            const int gc = col0 + wn + nt*8 + ec;
            float2 v0 = make_float2(acc[mt][nt][0], acc[mt][nt][1]);
            float2 v1 = make_float2(acc[mt][nt][2], acc[mt][nt][3]);
            if (ADD_SKIP) {
                float2 s0 = *reinterpret_cast<const float2*>(skip + (size_t)gr * N + gc);
                float2 s1 = *reinterpret_cast<const float2*>(skip + (size_t)(gr+8) * N + gc);
                v0.x += s0.x; v0.y += s0.y; v1.x += s1.x; v1.y += s1.y;
            }
            *reinterpret_cast<float2*>(C + (size_t)gr * N + gc)     = v0;
            *reinterpret_cast<float2*>(C + (size_t)(gr+8) * N + gc) = v1;
        }
    }
}

// ---------------------------------------------------------------------------
// Banded attention. Grid: (L/QT, H, B), 256 threads, dynamic smem:
//   Ks[192*64] fp32 (K tile, reused for V tile), Ps[64*196] fp32 (scores).
// 4 threads/query (part = tid&3), 48 keys each. Scores live in smem, so
// register peak is qf[64] (QK) or acc[64] (PV) -> no spills, 2 CTAs/SM.
// Epilogue writes bf16-split att [hi|hi|lo].
// ---------------------------------------------------------------------------
__global__ __launch_bounds__(256, 2) void attn_kernel(
    const float* __restrict__ qkv, __nv_bfloat16* __restrict__ attb)
{
    extern __shared__ __align__(16) float asm_[];
    float* Ks = asm_;                 // KT*DH floats (48 KB)
    float* Ps = asm_ + KT * DH;       // QT*PROW floats (~49 KB)

    const int qt = blockIdx.x, h = blockIdx.y, b = blockIdx.z;
    const int q0 = qt * QT;
    const int k0 = q0 - 64;
    const int tid  = threadIdx.x;
    const int part = tid & 3;
    const int q    = tid >> 2;
    const size_t base = (size_t)b * LSEQ * QKVC;
    float* prow = &Ps[q * PROW + part * 48];

    // ---- K tile ----
    for (int idx = tid; idx < KT * (DH/4); idx += 256) {
        const int j = idx >> 4, dc = idx & 15;
        const int kg = k0 + j;
        float4 val = make_float4(0.f, 0.f, 0.f, 0.f);
        if (kg >= 0 && kg < LSEQ)
            val = *reinterpret_cast<const float4*>(
                qkv + base + (size_t)kg * QKVC + DMODEL + h*DH + dc*4);
        *reinterpret_cast<float4*>(&Ks[j*DH + dc*4]) = val;
    }
    __syncthreads();

    // ---- QK scores -> Ps (masked, scaled); track local max ----
    float mx = -1e30f;
    {
        float qf[DH];
        const float4* qp = reinterpret_cast<const float4*>(
            qkv + base + (size_t)(q0 + q) * QKVC + h*DH);
        #pragma unroll
        for (int dc = 0; dc < 16; dc++) {
            float4 v = qp[dc];
            qf[dc*4+0] = v.x; qf[dc*4+1] = v.y; qf[dc*4+2] = v.z; qf[dc*4+3] = v.w;
        }
        #pragma unroll 4
        for (int jj = 0; jj < 48; jj++) {
            const int j = part * 48 + jj;
            float s = 0.0f;
            const float4* kp = reinterpret_cast<const float4*>(&Ks[j*DH]);
            #pragma unroll
            for (int dc = 0; dc < 16; dc++) {
                float4 kv = kp[dc];
                s += qf[dc*4+0]*kv.x + qf[dc*4+1]*kv.y
                   + qf[dc*4+2]*kv.z + qf[dc*4+3]*kv.w;
            }
            s *= 0.125f;
            const int kg = k0 + j;
            const bool valid = (j >= q) && (j <= q + 128) && (kg >= 0) && (kg < LSEQ);
            s = valid ? s : -1e30f;
            prow[jj] = s;
            mx = fmaxf(mx, s);
        }
    }
    mx = fmaxf(mx, __shfl_xor_sync(0xffffffffu, mx, 1));
    mx = fmaxf(mx, __shfl_xor_sync(0xffffffffu, mx, 2));

    // all K reads done -> safe to overwrite Ks with V
    __syncthreads();
    for (int idx = tid; idx < KT * (DH/4); idx += 256) {
        const int j = idx >> 4, dc = idx & 15;
        const int kg = k0 + j;
        float4 val = make_float4(0.f, 0.f, 0.f, 0.f);
        if (kg >= 0 && kg < LSEQ)
            val = *reinterpret_cast<const float4*>(
                qkv + base + (size_t)kg * QKVC + 2*DMODEL + h*DH + dc*4);
        *reinterpret_cast<float4*>(&Ks[j*DH + dc*4]) = val;
    }

    // exp pass on own Ps entries (no cross-thread deps; overlaps V load)
    float sum = 0.0f;
    #pragma unroll 4
    for (int jj = 0; jj < 48; jj++) {
        const float e = __expf(prow[jj] - mx);
        prow[jj] = e;
        sum += e;
    }
    sum += __shfl_xor_sync(0xffffffffu, sum, 1);
    sum += __shfl_xor_sync(0xffffffffu, sum, 2);
    const float inv = 1.0f / sum;             // self-key always valid => sum > 0
    __syncthreads();                          // V tile complete

    // ---- PV from smem ----
    float acc[DH];
    #pragma unroll
    for (int d = 0; d < DH; d++) acc[d] = 0.0f;
    #pragma unroll 2
    for (int jj = 0; jj < 48; jj++) {
        const float pv = prow[jj];            // e (unnormalized)
        const int j = part * 48 + jj;
        const float4* vp = reinterpret_cast<const float4*>(&Ks[j*DH]);
        #pragma unroll
        for (int dc = 0; dc < 16; dc++) {
            float4 v = vp[dc];
            acc[dc*4+0] += pv * v.x; acc[dc*4+1] += pv * v.y;
            acc[dc*4+2] += pv * v.z; acc[dc*4+3] += pv * v.w;
        }
    }
    #pragma unroll
    for (int d = 0; d < DH; d++) {
        float r = acc[d] * inv;
        r += __shfl_xor_sync(0xffffffffu, r, 1);
        r += __shfl_xor_sync(0xffffffffu, r, 2);
        acc[d] = r;
    }
    if (part == 0) {
        __nv_bfloat16* rowb = attb + ((size_t)b * LSEQ + q0 + q) * K3;
        #pragma unroll
        for (int dc = 0; dc < 16; dc++) {
            __nv_bfloat16 hh[4], ll[4];
            #pragma unroll
            for (int i = 0; i < 4; i++) {
                const float v = acc[dc*4+i];
                hh[i] = __float2bfloat16(v);
                ll[i] = __float2bfloat16(v - __bfloat162float(hh[i]));
            }
            const int c = h*DH + dc*4;
            *reinterpret_cast<uint2*>(&rowb[c])            = *reinterpret_cast<uint2*>(hh);
            *reinterpret_cast<uint2*>(&rowb[DMODEL + c])   = *reinterpret_cast<uint2*>(hh);
            *reinterpret_cast<uint2*>(&rowb[2*DMODEL + c]) = *reinterpret_cast<uint2*>(ll);
        }
    }
}

// ---------------------------------------------------------------------------
// Launch
// ---------------------------------------------------------------------------
extern "C" void kernel_launch(void* const* d_in, const int* in_sizes, int n_in,
                              void* d_out, int out_size)
{
    const float* x      = (const float*)d_in[0];
    const float* w_norm = (const float*)d_in[1];
    const float* w_qkv  = (const float*)d_in[2];
    const float* w_out  = (const float*)d_in[3];
    float* out = (float*)d_out;

    float *qkv_p;
    __nv_bfloat16 *xnb_p, *attb_p, *wqkvb_p, *woutb_p;
    cudaGetSymbolAddress((void**)&qkv_p,   g_qkv);
    cudaGetSymbolAddress((void**)&xnb_p,   g_xnb);
    cudaGetSymbolAddress((void**)&attb_p,  g_attb);
    cudaGetSymbolAddress((void**)&wqkvb_p, g_wqkvb);
    cudaGetSymbolAddress((void**)&woutb_p, g_woutb);

    // opt-in dynamic smem (host-side attribute set; graph-capture safe)
    cudaFuncSetAttribute(gemm_bf16_mma<false>,
                         cudaFuncAttributeMaxDynamicSharedMemorySize, GEMM_SMEM);
    cudaFuncSetAttribute(gemm_bf16_mma<true>,
                         cudaFuncAttributeMaxDynamicSharedMemorySize, GEMM_SMEM);
    cudaFuncSetAttribute(attn_kernel,
                         cudaFuncAttributeMaxDynamicSharedMemorySize, ATTN_SMEM);

    // 1) RMSNorm + bf16 split of activations
    rmsnorm_split_kernel<<<ROWS, 256>>>(x, w_norm, xnb_p);

    // 1b) weight splits
    split_w_kernel<<<(QKVC * DMODEL + 255) / 256, 256>>>(w_qkv, wqkvb_p, QKVC * DMODEL);
    split_w_kernel<<<(DMODEL * DMODEL + 255) / 256, 256>>>(w_out, woutb_p, DMODEL * DMODEL);

    // 2) QKV GEMM (HMMA): [4096,3072] fp32
    {
        dim3 grid(QKVC / 128, ROWS / 128);   // (24, 32)
        gemm_bf16_mma<false><<<grid, 256, GEMM_SMEM>>>(xnb_p, wqkvb_p, nullptr, qkv_p, QKVC);
    }

    // 3) Banded attention (fp32), writes bf16-split att
    {
        dim3 grid(LSEQ / QT, NHEADS, BATCH); // (32, 16, 2)
        attn_kernel<<<grid, 256, ATTN_SMEM>>>(qkv_p, attb_p);
    }

    // 4) out GEMM (HMMA) + skip: [4096,1024] fp32
    {
        dim3 grid(DMODEL / 128, ROWS / 128); // (8, 32)
        gemm_bf16_mma<true><<<grid, 256, GEMM_SMEM>>>(attb_p, woutb_p, x, out, DMODEL);
    }
}

// round 7
// speedup vs baseline: 2.7616x; 1.8002x over previous
#include <cuda_runtime.h>
#include <cuda_bf16.h>
#include <cstdint>

// Problem constants (fixed by setup_inputs)
#define BATCH 2
#define LSEQ  2048
#define DMODEL 1024
#define NHEADS 16
#define DH 64
#define ROWS (BATCH * LSEQ)          // 4096
#define QKVC (3 * DMODEL)            // 3072
#define QT   64                      // queries per attention CTA
#define KT   192                     // keys per attention CTA (64 + 128)
#define KROW 68                      // padded K/V smem row stride (floats)
#define PROW 196                     // Ps row stride (floats); parts at +49 each

#define K3   (3 * DMODEL)            // bf16-split concatenated K = 3072
#define BK   32                      // bf16 k per smem tile
#define NKT3 (K3 / BK)               // 96 k-tiles
#define SMROW 80                     // padded smem row bytes (64B data + 16B pad)
#define STAGE_BYTES (128 * SMROW)    // 10240 B per matrix per stage
#define GEMM_SMEM (3 * 2 * STAGE_BYTES)            // 61440 B
#define ATTN_SMEM ((KT * KROW + QT * PROW) * 4)    // 102400 B

// ---------------------------------------------------------------------------
// Scratch (device globals; no allocation at runtime)
// ---------------------------------------------------------------------------
__device__ float          g_qkv   [ROWS * QKVC];     // fp32 qkv (48 MB)
__device__ __nv_bfloat16  g_xnb   [ROWS * K3];       // xn split [hi|hi|lo]
__device__ __nv_bfloat16  g_attb  [ROWS * K3];       // att split [hi|hi|lo]
__device__ __nv_bfloat16  g_wqkvb [QKVC * K3];       // w_qkv split [hi|lo|hi]
__device__ __nv_bfloat16  g_woutb [DMODEL * K3];     // w_out split [hi|lo|hi]

// ---------------------------------------------------------------------------
// Baseline-ISA helpers (sm_80-class only: cp.async, ldmatrix, mma.sync)
// ---------------------------------------------------------------------------
__device__ __forceinline__ uint32_t smem_u32(const void* p) {
    uint32_t a;
    asm("{ .reg .u64 t; cvta.to.shared.u64 t, %1; cvt.u32.u64 %0, t; }"
        : "=r"(a) : "l"(p));
    return a;
}
__device__ __forceinline__ void cp16(uint32_t s, const void* g) {
    asm volatile("cp.async.cg.shared.global [%0], [%1], 16;"
                 :: "r"(s), "l"(g) : "memory");
}
#define CP_COMMIT() asm volatile("cp.async.commit_group;" ::: "memory")
#define CP_WAIT(n)  asm volatile("cp.async.wait_group %0;" :: "n"(n) : "memory")

__device__ __forceinline__ void ldmx4(uint32_t* r, uint32_t addr) {
    asm volatile("ldmatrix.sync.aligned.m8n8.x4.shared.b16 {%0,%1,%2,%3}, [%4];"
                 : "=r"(r[0]), "=r"(r[1]), "=r"(r[2]), "=r"(r[3]) : "r"(addr));
}
__device__ __forceinline__ void mma16816(float* d, const uint32_t* a,
                                         uint32_t b0, uint32_t b1) {
    asm volatile(
        "mma.sync.aligned.m16n8k16.row.col.f32.bf16.bf16.f32 "
        "{%0,%1,%2,%3}, {%4,%5,%6,%7}, {%8,%9}, {%0,%1,%2,%3};"
        : "+f"(d[0]), "+f"(d[1]), "+f"(d[2]), "+f"(d[3])
        : "r"(a[0]), "r"(a[1]), "r"(a[2]), "r"(a[3]), "r"(b0), "r"(b1));
}

// ---------------------------------------------------------------------------
// RMSNorm fused with bf16 split: writes [hi|hi|lo] activation layout
// ---------------------------------------------------------------------------
__global__ __launch_bounds__(256) void rmsnorm_split_kernel(
    const float* __restrict__ x, const float* __restrict__ w,
    __nv_bfloat16* __restrict__ xb)
{
    const int row = blockIdx.x;
    const float4* xr = reinterpret_cast<const float4*>(x + (size_t)row * DMODEL);
    float4 v = xr[threadIdx.x];
    float ss = v.x*v.x + v.y*v.y + v.z*v.z + v.w*v.w;

    #pragma unroll
    for (int o = 16; o > 0; o >>= 1)
        ss += __shfl_xor_sync(0xffffffffu, ss, o);

    __shared__ float red[8];
    const int wid = threadIdx.x >> 5, lane = threadIdx.x & 31;
    if (lane == 0) red[wid] = ss;
    __syncthreads();
    if (wid == 0) {
        float t = (lane < 8) ? red[lane] : 0.0f;
        #pragma unroll
        for (int o = 4; o > 0; o >>= 1)
            t += __shfl_xor_sync(0xffffffffu, t, o);
        if (lane == 0) red[0] = rsqrtf(t * (1.0f / DMODEL) + 1e-6f);
    }
    __syncthreads();
    const float s = red[0];
    float4 wv = reinterpret_cast<const float4*>(w)[threadIdx.x];
    float o4[4] = { v.x*s*wv.x, v.y*s*wv.y, v.z*s*wv.z, v.w*s*wv.w };

    __nv_bfloat16 h[4], l[4];
    #pragma unroll
    for (int i = 0; i < 4; i++) {
        h[i] = __float2bfloat16(o4[i]);
        l[i] = __float2bfloat16(o4[i] - __bfloat162float(h[i]));
    }
    __nv_bfloat16* rowb = xb + (size_t)row * K3;
    const int c = threadIdx.x * 4;
    *reinterpret_cast<uint2*>(&rowb[c])              = *reinterpret_cast<uint2*>(h);
    *reinterpret_cast<uint2*>(&rowb[DMODEL + c])     = *reinterpret_cast<uint2*>(h);
    *reinterpret_cast<uint2*>(&rowb[2*DMODEL + c])   = *reinterpret_cast<uint2*>(l);
}

// ---------------------------------------------------------------------------
// Weight split: [hi|lo|hi] layout
// ---------------------------------------------------------------------------
__global__ __launch_bounds__(256) void split_w_kernel(
    const float* __restrict__ W, __nv_bfloat16* __restrict__ Wb, int total)
{
    int i = blockIdx.x * blockDim.x + threadIdx.x;
    if (i >= total) return;
    const int r = i >> 10, c = i & 1023;
    float x = W[i];
    __nv_bfloat16 h = __float2bfloat16(x);
    __nv_bfloat16 l = __float2bfloat16(x - __bfloat162float(h));
    __nv_bfloat16* row = Wb + (size_t)r * K3;
    row[c]              = h;
    row[DMODEL + c]     = l;
    row[2*DMODEL + c]   = h;
}

// ---------------------------------------------------------------------------
// bf16 HMMA GEMM (NT over split-K3): C[m,n] = sum_k3 A[m,k3]*B[n,k3] (+skip)
// 128x128 CTA tile, BK=32, 3-stage cp.async pipeline (dynamic smem),
// 8 warps (warp tile 64x32), mma.sync.m16n8k16 bf16 -> fp32.
// ---------------------------------------------------------------------------
template <bool ADD_SKIP>
__global__ __launch_bounds__(256, 2) void gemm_bf16_mma(
    const __nv_bfloat16* __restrict__ A, const __nv_bfloat16* __restrict__ B,
    const float* __restrict__ skip, float* __restrict__ C, int N)
{
    extern __shared__ __align__(16) char dynsm[];

    const int tid  = threadIdx.x;
    const int warp = tid >> 5, lane = tid & 31;
    const int row0 = blockIdx.y * 128;
    const int col0 = blockIdx.x * 128;
    const int wm = (warp >> 2) * 64;    // 0 or 64
    const int wn = (warp & 3) * 32;     // 0,32,64,96

    const uint32_t sA = smem_u32(dynsm);                     // 3 stages A
    const uint32_t sB = sA + 3 * STAGE_BYTES;                // 3 stages B

    // loader: 512 16B-chunks per matrix per tile; 2 per thread
    const int c0 = tid, c1 = tid + 256;
    const int r0c = c0 >> 2, k0c = (c0 & 3);
    const int r1c = c1 >> 2, k1c = (c1 & 3);
    const __nv_bfloat16* Ag0 = A + (size_t)(row0 + r0c) * K3 + k0c * 8;
    const __nv_bfloat16* Ag1 = A + (size_t)(row0 + r1c) * K3 + k1c * 8;
    const __nv_bfloat16* Bg0 = B + (size_t)(col0 + r0c) * K3 + k0c * 8;
    const __nv_bfloat16* Bg1 = B + (size_t)(col0 + r1c) * K3 + k1c * 8;
    const uint32_t stA0 = sA + r0c * SMROW + k0c * 16;
    const uint32_t stA1 = sA + r1c * SMROW + k1c * 16;
    const uint32_t stB0 = sB + r0c * SMROW + k0c * 16;
    const uint32_t stB1 = sB + r1c * SMROW + k1c * 16;

    float acc[4][4][4];
    #pragma unroll
    for (int i = 0; i < 4; i++)
        #pragma unroll
        for (int j = 0; j < 4; j++)
            #pragma unroll
            for (int f = 0; f < 4; f++) acc[i][j][f] = 0.0f;

    // ldmatrix per-lane address components
    const int arow = lane & 15;                       // A: row within m16
    const int asel = (lane >> 4) * 16;                // A: 0 or 16 bytes (k half)
    const int brow = (lane & 7) + ((lane >> 4) << 3); // B: n within n16
    const int bsel = ((lane >> 3) & 1) * 16;          // B: k half bytes

    // prologue: stages 0,1
    #pragma unroll
    for (int st = 0; st < 2; st++) {
        const uint32_t so = (uint32_t)st * STAGE_BYTES;
        const int ko = st * BK;
        cp16(stA0 + so, Ag0 + ko); cp16(stA1 + so, Ag1 + ko);
        cp16(stB0 + so, Bg0 + ko); cp16(stB1 + so, Bg1 + ko);
        CP_COMMIT();
    }

    int stg = 0;
    for (int kt = 0; kt < NKT3; kt++) {
        if (kt + 2 < NKT3) {
            const uint32_t so = (uint32_t)((kt + 2) % 3) * STAGE_BYTES;
            const int ko = (kt + 2) * BK;
            cp16(stA0 + so, Ag0 + ko); cp16(stA1 + so, Ag1 + ko);
            cp16(stB0 + so, Bg0 + ko); cp16(stB1 + so, Bg1 + ko);
            CP_COMMIT();
            CP_WAIT(2);
        } else if (kt + 1 < NKT3) {
            CP_WAIT(1);
        } else {
            CP_WAIT(0);
        }
        __syncthreads();

        const uint32_t so = (uint32_t)stg * STAGE_BYTES;
        #pragma unroll
        for (int s = 0; s < 2; s++) {          // two k16 steps per BK=32
            uint32_t afr[4][4];
            #pragma unroll
            for (int mt = 0; mt < 4; mt++)
                ldmx4(afr[mt], sA + so + (uint32_t)((wm + mt*16 + arow) * SMROW
                                                    + s*32 + asel));
            uint32_t bfr[2][4];
            #pragma unroll
            for (int nq = 0; nq < 2; nq++)
                ldmx4(bfr[nq], sB + so + (uint32_t)((wn + nq*16 + brow) * SMROW
                                                    + s*32 + bsel));
            #pragma unroll
            for (int mt = 0; mt < 4; mt++)
                #pragma unroll
                for (int nt = 0; nt < 4; nt++)
                    mma16816(acc[mt][nt], afr[mt],
                             bfr[nt >> 1][(nt & 1) * 2],
                             bfr[nt >> 1][(nt & 1) * 2 + 1]);
        }
        __syncthreads();
        stg = (stg + 1) % 3;
    }

    // epilogue: frag layout m16n8: (c0,c1)->row g, cols 2t,2t+1; (c2,c3)->row g+8
    const int er = lane >> 2, ec = (lane & 3) * 2;
    #pragma unroll
    for (int mt = 0; mt < 4; mt++) {
        #pragma unroll
        for (int nt = 0; nt < 4; nt++) {
            const int gr = row0 + wm + mt*16 + er;
            const int gc = col0 + wn + nt*8 + ec;
            float2 v0 = make_float2(acc[mt][nt][0], acc[mt][nt][1]);
            float2 v1 = make_float2(acc[mt][nt][2], acc[mt][nt][3]);
            if (ADD_SKIP) {
                float2 s0 = *reinterpret_cast<const float2*>(skip + (size_t)gr * N + gc);
                float2 s1 = *reinterpret_cast<const float2*>(skip + (size_t)(gr+8) * N + gc);
                v0.x += s0.x; v0.y += s0.y; v1.x += s1.x; v1.y += s1.y;
            }
            *reinterpret_cast<float2*>(C + (size_t)gr * N + gc)     = v0;
            *reinterpret_cast<float2*>(C + (size_t)(gr+8) * N + gc) = v1;
        }
    }
}

// ---------------------------------------------------------------------------
// Banded attention. Grid: (L/QT, H, B), 256 threads, dynamic smem:
//   Ks[192 rows x stride 68] fp32 (K tile, reused for V), Ps[64 x 196].
// 4 threads/query (part = tid&3); part owns keys j = 4*jj + part (interleaved)
// -> the 4 partner rows are consecutive; with the 68-float row stride their
// bank starts differ by 4 words => conflict-free LDS.128 (queries broadcast).
// Epilogue writes bf16-split att [hi|hi|lo].
// ---------------------------------------------------------------------------
__global__ __launch_bounds__(256, 2) void attn_kernel(
    const float* __restrict__ qkv, __nv_bfloat16* __restrict__ attb)
{
    extern __shared__ __align__(16) float asm_[];
    float* Ks = asm_;                 // KT*KROW floats (~51 KB)
    float* Ps = asm_ + KT * KROW;     // QT*PROW floats (~49 KB)

    const int qt = blockIdx.x, h = blockIdx.y, b = blockIdx.z;
    const int q0 = qt * QT;
    const int k0 = q0 - 64;
    const int tid  = threadIdx.x;
    const int part = tid & 3;
    const int q    = tid >> 2;
    const size_t base = (size_t)b * LSEQ * QKVC;
    float* prow = &Ps[q * PROW + part * 49];   // 49: conflict-free part stride

    // ---- K tile (row stride KROW) ----
    for (int idx = tid; idx < KT * (DH/4); idx += 256) {
        const int j = idx >> 4, dc = idx & 15;
        const int kg = k0 + j;
        float4 val = make_float4(0.f, 0.f, 0.f, 0.f);
        if (kg >= 0 && kg < LSEQ)
            val = *reinterpret_cast<const float4*>(
                qkv + base + (size_t)kg * QKVC + DMODEL + h*DH + dc*4);
        *reinterpret_cast<float4*>(&Ks[j*KROW + dc*4]) = val;
    }
    __syncthreads();

    // ---- QK scores -> Ps (masked, scaled); track local max ----
    float mx = -1e30f;
    {
        float qf[DH];
        const float4* qp = reinterpret_cast<const float4*>(
            qkv + base + (size_t)(q0 + q) * QKVC + h*DH);
        #pragma unroll
        for (int dc = 0; dc < 16; dc++) {
            float4 v = qp[dc];
            qf[dc*4+0] = v.x; qf[dc*4+1] = v.y; qf[dc*4+2] = v.z; qf[dc*4+3] = v.w;
        }
        #pragma unroll 4
        for (int jj = 0; jj < 48; jj++) {
            const int j = jj * 4 + part;          // interleaved key ownership
            float s = 0.0f;
            const float4* kp = reinterpret_cast<const float4*>(&Ks[j*KROW]);
            #pragma unroll
            for (int dc = 0; dc < 16; dc++) {
                float4 kv = kp[dc];
                s += qf[dc*4+0]*kv.x + qf[dc*4+1]*kv.y
                   + qf[dc*4+2]*kv.z + qf[dc*4+3]*kv.w;
            }
            s *= 0.125f;
            const int kg = k0 + j;
            const bool valid = (j >= q) && (j <= q + 128) && (kg >= 0) && (kg < LSEQ);
            s = valid ? s : -1e30f;
            prow[jj] = s;
            mx = fmaxf(mx, s);
        }
    }
    mx = fmaxf(mx, __shfl_xor_sync(0xffffffffu, mx, 1));
    mx = fmaxf(mx, __shfl_xor_sync(0xffffffffu, mx, 2));

    // all K reads done -> safe to overwrite Ks with V
    __syncthreads();
    for (int idx = tid; idx < KT * (DH/4); idx += 256) {
        const int j = idx >> 4, dc = idx & 15;
        const int kg = k0 + j;
        float4 val = make_float4(0.f, 0.f, 0.f, 0.f);
        if (kg >= 0 && kg < LSEQ)
            val = *reinterpret_cast<const float4*>(
                qkv + base + (size_t)kg * QKVC + 2*DMODEL + h*DH + dc*4);
        *reinterpret_cast<float4*>(&Ks[j*KROW + dc*4]) = val;
    }

    // exp pass on own Ps entries (no cross-thread deps; overlaps V load)
    float sum = 0.0f;
    #pragma unroll 4
    for (int jj = 0; jj < 48; jj++) {
        const float e = __expf(prow[jj] - mx);
        prow[jj] = e;
        sum += e;
    }
    sum += __shfl_xor_sync(0xffffffffu, sum, 1);
    sum += __shfl_xor_sync(0xffffffffu, sum, 2);
    const float inv = 1.0f / sum;             // self-key always valid => sum > 0
    __syncthreads();                          // V tile complete

    // ---- PV from smem ----
    float acc[DH];
    #pragma unroll
    for (int d = 0; d < DH; d++) acc[d] = 0.0f;
    #pragma unroll 2
    for (int jj = 0; jj < 48; jj++) {
        const float pv = prow[jj];            // e (unnormalized)
        const int j = jj * 4 + part;
        const float4* vp = reinterpret_cast<const float4*>(&Ks[j*KROW]);
        #pragma unroll
        for (int dc = 0; dc < 16; dc++) {
            float4 v = vp[dc];
            acc[dc*4+0] += pv * v.x; acc[dc*4+1] += pv * v.y;
            acc[dc*4+2] += pv * v.z; acc[dc*4+3] += pv * v.w;
        }
    }
    #pragma unroll
    for (int d = 0; d < DH; d++) {
        float r = acc[d] * inv;
        r += __shfl_xor_sync(0xffffffffu, r, 1);
        r += __shfl_xor_sync(0xffffffffu, r, 2);
        acc[d] = r;
    }
    if (part == 0) {
        __nv_bfloat16* rowb = attb + ((size_t)b * LSEQ + q0 + q) * K3;
        #pragma unroll
        for (int dc = 0; dc < 16; dc++) {
            __nv_bfloat16 hh[4], ll[4];
            #pragma unroll
            for (int i = 0; i < 4; i++) {
                const float v = acc[dc*4+i];
                hh[i] = __float2bfloat16(v);
                ll[i] = __float2bfloat16(v - __bfloat162float(hh[i]));
            }
            const int c = h*DH + dc*4;
            *reinterpret_cast<uint2*>(&rowb[c])            = *reinterpret_cast<uint2*>(hh);
            *reinterpret_cast<uint2*>(&rowb[DMODEL + c])   = *reinterpret_cast<uint2*>(hh);
            *reinterpret_cast<uint2*>(&rowb[2*DMODEL + c]) = *reinterpret_cast<uint2*>(ll);
        }
    }
}

// ---------------------------------------------------------------------------
// Launch
// ---------------------------------------------------------------------------
extern "C" void kernel_launch(void* const* d_in, const int* in_sizes, int n_in,
                              void* d_out, int out_size)
{
    const float* x      = (const float*)d_in[0];
    const float* w_norm = (const float*)d_in[1];
    const float* w_qkv  = (const float*)d_in[2];
    const float* w_out  = (const float*)d_in[3];
    float* out = (float*)d_out;

    float *qkv_p;
    __nv_bfloat16 *xnb_p, *attb_p, *wqkvb_p, *woutb_p;
    cudaGetSymbolAddress((void**)&qkv_p,   g_qkv);
    cudaGetSymbolAddress((void**)&xnb_p,   g_xnb);
    cudaGetSymbolAddress((void**)&attb_p,  g_attb);
    cudaGetSymbolAddress((void**)&wqkvb_p, g_wqkvb);
    cudaGetSymbolAddress((void**)&woutb_p, g_woutb);

    // opt-in dynamic smem (host-side attribute set; graph-capture safe)
    cudaFuncSetAttribute(gemm_bf16_mma<false>,
                         cudaFuncAttributeMaxDynamicSharedMemorySize, GEMM_SMEM);
    cudaFuncSetAttribute(gemm_bf16_mma<true>,
                         cudaFuncAttributeMaxDynamicSharedMemorySize, GEMM_SMEM);
    cudaFuncSetAttribute(attn_kernel,
                         cudaFuncAttributeMaxDynamicSharedMemorySize, ATTN_SMEM);

    // 1) RMSNorm + bf16 split of activations
    rmsnorm_split_kernel<<<ROWS, 256>>>(x, w_norm, xnb_p);

    // 1b) weight splits
    split_w_kernel<<<(QKVC * DMODEL + 255) / 256, 256>>>(w_qkv, wqkvb_p, QKVC * DMODEL);
    split_w_kernel<<<(DMODEL * DMODEL + 255) / 256, 256>>>(w_out, woutb_p, DMODEL * DMODEL);

    // 2) QKV GEMM (HMMA): [4096,3072] fp32
    {
        dim3 grid(QKVC / 128, ROWS / 128);   // (24, 32)
        gemm_bf16_mma<false><<<grid, 256, GEMM_SMEM>>>(xnb_p, wqkvb_p, nullptr, qkv_p, QKVC);
    }

    // 3) Banded attention (fp32), writes bf16-split att
    {
        dim3 grid(LSEQ / QT, NHEADS, BATCH); // (32, 16, 2)
        attn_kernel<<<grid, 256, ATTN_SMEM>>>(qkv_p, attb_p);
    }

    // 4) out GEMM (HMMA) + skip: [4096,1024] fp32
    {
        dim3 grid(DMODEL / 128, ROWS / 128); // (8, 32)
        gemm_bf16_mma<true><<<grid, 256, GEMM_SMEM>>>(attb_p, woutb_p, x, out, DMODEL);
    }
}

// round 8
// speedup vs baseline: 2.7617x; 1.0000x over previous
#include <cuda_runtime.h>
#include <cuda_bf16.h>
#include <cstdint>

// Problem constants (fixed by setup_inputs)
#define BATCH 2
#define LSEQ  2048
#define DMODEL 1024
#define NHEADS 16
#define DH 64
#define ROWS (BATCH * LSEQ)          // 4096
#define QKVC (3 * DMODEL)            // 3072
#define QT   64                      // queries per attention CTA
#define KT   192                     // keys per attention CTA (64 + 128)
#define KROW 68                      // padded K/V smem row stride (floats)
#define PROW 196                     // Ps row stride (floats); parts at +49 each

#define K3   (3 * DMODEL)            // bf16-split concatenated K = 3072
#define BK   32                      // bf16 k per smem tile
#define NKT3 (K3 / BK)               // 96 k-tiles
#define SMROW 80                     // padded smem row bytes (64B data + 16B pad)
#define STAGE_BYTES (128 * SMROW)    // 10240 B per matrix per stage
#define GEMM_SMEM (3 * 2 * STAGE_BYTES)            // 61440 B
#define ATTN_SMEM ((KT * KROW + QT * PROW) * 4)    // 102400 B

// ---------------------------------------------------------------------------
// Scratch (device globals; no allocation at runtime)
// ---------------------------------------------------------------------------
__device__ float          g_qkv   [ROWS * QKVC];     // fp32 qkv (48 MB)
__device__ __nv_bfloat16  g_xnb   [ROWS * K3];       // xn split [hi|hi|lo]
__device__ __nv_bfloat16  g_attb  [ROWS * K3];       // att split [hi|hi|lo]
__device__ __nv_bfloat16  g_wqkvb [QKVC * K3];       // w_qkv split [hi|lo|hi]
__device__ __nv_bfloat16  g_woutb [DMODEL * K3];     // w_out split [hi|lo|hi]

// ---------------------------------------------------------------------------
// Baseline-ISA helpers (sm_80-class only: cp.async, ldmatrix, mma.sync)
// ---------------------------------------------------------------------------
__device__ __forceinline__ uint32_t smem_u32(const void* p) {
    uint32_t a;
    asm("{ .reg .u64 t; cvta.to.shared.u64 t, %1; cvt.u32.u64 %0, t; }"
        : "=r"(a) : "l"(p));
    return a;
}
__device__ __forceinline__ void cp16(uint32_t s, const void* g) {
    asm volatile("cp.async.cg.shared.global [%0], [%1], 16;"
                 :: "r"(s), "l"(g) : "memory");
}
#define CP_COMMIT() asm volatile("cp.async.commit_group;" ::: "memory")
#define CP_WAIT(n)  asm volatile("cp.async.wait_group %0;" :: "n"(n) : "memory")

__device__ __forceinline__ void ldmx4(uint32_t* r, uint32_t addr) {
    asm volatile("ldmatrix.sync.aligned.m8n8.x4.shared.b16 {%0,%1,%2,%3}, [%4];"
                 : "=r"(r[0]), "=r"(r[1]), "=r"(r[2]), "=r"(r[3]) : "r"(addr));
}
__device__ __forceinline__ void mma16816(float* d, const uint32_t* a,
                                         uint32_t b0, uint32_t b1) {
    asm volatile(
        "mma.sync.aligned.m16n8k16.row.col.f32.bf16.bf16.f32 "
        "{%0,%1,%2,%3}, {%4,%5,%6,%7}, {%8,%9}, {%0,%1,%2,%3};"
        : "+f"(d[0]), "+f"(d[1]), "+f"(d[2]), "+f"(d[3])
        : "r"(a[0]), "r"(a[1]), "r"(a[2]), "r"(a[3]), "r"(b0), "r"(b1));
}

// ---------------------------------------------------------------------------
// RMSNorm fused with bf16 split: writes [hi|hi|lo] activation layout
// ---------------------------------------------------------------------------
__global__ __launch_bounds__(256) void rmsnorm_split_kernel(
    const float* __restrict__ x, const float* __restrict__ w,
    __nv_bfloat16* __restrict__ xb)
{
    const int row = blockIdx.x;
    const float4* xr = reinterpret_cast<const float4*>(x + (size_t)row * DMODEL);
    float4 v = xr[threadIdx.x];
    float ss = v.x*v.x + v.y*v.y + v.z*v.z + v.w*v.w;

    #pragma unroll
    for (int o = 16; o > 0; o >>= 1)
        ss += __shfl_xor_sync(0xffffffffu, ss, o);

    __shared__ float red[8];
    const int wid = threadIdx.x >> 5, lane = threadIdx.x & 31;
    if (lane == 0) red[wid] = ss;
    __syncthreads();
    if (wid == 0) {
        float t = (lane < 8) ? red[lane] : 0.0f;
        #pragma unroll
        for (int o = 4; o > 0; o >>= 1)
            t += __shfl_xor_sync(0xffffffffu, t, o);
        if (lane == 0) red[0] = rsqrtf(t * (1.0f / DMODEL) + 1e-6f);
    }
    __syncthreads();
    const float s = red[0];
    float4 wv = reinterpret_cast<const float4*>(w)[threadIdx.x];
    float o4[4] = { v.x*s*wv.x, v.y*s*wv.y, v.z*s*wv.z, v.w*s*wv.w };

    __nv_bfloat16 h[4], l[4];
    #pragma unroll
    for (int i = 0; i < 4; i++) {
        h[i] = __float2bfloat16(o4[i]);
        l[i] = __float2bfloat16(o4[i] - __bfloat162float(h[i]));
    }
    __nv_bfloat16* rowb = xb + (size_t)row * K3;
    const int c = threadIdx.x * 4;
    *reinterpret_cast<uint2*>(&rowb[c])              = *reinterpret_cast<uint2*>(h);
    *reinterpret_cast<uint2*>(&rowb[DMODEL + c])     = *reinterpret_cast<uint2*>(h);
    *reinterpret_cast<uint2*>(&rowb[2*DMODEL + c])   = *reinterpret_cast<uint2*>(l);
}

// ---------------------------------------------------------------------------
// Weight split: [hi|lo|hi] layout
// ---------------------------------------------------------------------------
__global__ __launch_bounds__(256) void split_w_kernel(
    const float* __restrict__ W, __nv_bfloat16* __restrict__ Wb, int total)
{
    int i = blockIdx.x * blockDim.x + threadIdx.x;
    if (i >= total) return;
    const int r = i >> 10, c = i & 1023;
    float x = W[i];
    __nv_bfloat16 h = __float2bfloat16(x);
    __nv_bfloat16 l = __float2bfloat16(x - __bfloat162float(h));
    __nv_bfloat16* row = Wb + (size_t)r * K3;
    row[c]              = h;
    row[DMODEL + c]     = l;
    row[2*DMODEL + c]   = h;
}

// ---------------------------------------------------------------------------
// bf16 HMMA GEMM (NT over split-K3): C[m,n] = sum_k3 A[m,k3]*B[n,k3] (+skip)
// 128x128 CTA tile, BK=32, 3-stage cp.async pipeline (dynamic smem),
// 8 warps (warp tile 64x32), mma.sync.m16n8k16 bf16 -> fp32.
// ---------------------------------------------------------------------------
template <bool ADD_SKIP>
__global__ __launch_bounds__(256, 2) void gemm_bf16_mma(
    const __nv_bfloat16* __restrict__ A, const __nv_bfloat16* __restrict__ B,
    const float* __restrict__ skip, float* __restrict__ C, int N)
{
    extern __shared__ __align__(16) char dynsm[];

    const int tid  = threadIdx.x;
    const int warp = tid >> 5, lane = tid & 31;
    const int row0 = blockIdx.y * 128;
    const int col0 = blockIdx.x * 128;
    const int wm = (warp >> 2) * 64;    // 0 or 64
    const int wn = (warp & 3) * 32;     // 0,32,64,96

    const uint32_t sA = smem_u32(dynsm);                     // 3 stages A
    const uint32_t sB = sA + 3 * STAGE_BYTES;                // 3 stages B

    // loader: 512 16B-chunks per matrix per tile; 2 per thread
    const int c0 = tid, c1 = tid + 256;
    const int r0c = c0 >> 2, k0c = (c0 & 3);
    const int r1c = c1 >> 2, k1c = (c1 & 3);
    const __nv_bfloat16* Ag0 = A + (size_t)(row0 + r0c) * K3 + k0c * 8;
    const __nv_bfloat16* Ag1 = A + (size_t)(row0 + r1c) * K3 + k1c * 8;
    const __nv_bfloat16* Bg0 = B + (size_t)(col0 + r0c) * K3 + k0c * 8;
    const __nv_bfloat16* Bg1 = B + (size_t)(col0 + r1c) * K3 + k1c * 8;
    const uint32_t stA0 = sA + r0c * SMROW + k0c * 16;
    const uint32_t stA1 = sA + r1c * SMROW + k1c * 16;
    const uint32_t stB0 = sB + r0c * SMROW + k0c * 16;
    const uint32_t stB1 = sB + r1c * SMROW + k1c * 16;

    float acc[4][4][4];
    #pragma unroll
    for (int i = 0; i < 4; i++)
        #pragma unroll
        for (int j = 0; j < 4; j++)
            #pragma unroll
            for (int f = 0; f < 4; f++) acc[i][j][f] = 0.0f;

    // ldmatrix per-lane address components
    const int arow = lane & 15;                       // A: row within m16
    const int asel = (lane >> 4) * 16;                // A: 0 or 16 bytes (k half)
    const int brow = (lane & 7) + ((lane >> 4) << 3); // B: n within n16
    const int bsel = ((lane >> 3) & 1) * 16;          // B: k half bytes

    // prologue: stages 0,1
    #pragma unroll
    for (int st = 0; st < 2; st++) {
        const uint32_t so = (uint32_t)st * STAGE_BYTES;
        const int ko = st * BK;
        cp16(stA0 + so, Ag0 + ko); cp16(stA1 + so, Ag1 + ko);
        cp16(stB0 + so, Bg0 + ko); cp16(stB1 + so, Bg1 + ko);
        CP_COMMIT();
    }

    int stg = 0;
    for (int kt = 0; kt < NKT3; kt++) {
        if (kt + 2 < NKT3) {
            const uint32_t so = (uint32_t)((kt + 2) % 3) * STAGE_BYTES;
            const int ko = (kt + 2) * BK;
            cp16(stA0 + so, Ag0 + ko); cp16(stA1 + so, Ag1 + ko);
            cp16(stB0 + so, Bg0 + ko); cp16(stB1 + so, Bg1 + ko);
            CP_COMMIT();
            CP_WAIT(2);
        } else if (kt + 1 < NKT3) {
            CP_WAIT(1);
        } else {
            CP_WAIT(0);
        }
        __syncthreads();

        const uint32_t so = (uint32_t)stg * STAGE_BYTES;
        #pragma unroll
        for (int s = 0; s < 2; s++) {          // two k16 steps per BK=32
            uint32_t afr[4][4];
            #pragma unroll
            for (int mt = 0; mt < 4; mt++)
                ldmx4(afr[mt], sA + so + (uint32_t)((wm + mt*16 + arow) * SMROW
                                                    + s*32 + asel));
            uint32_t bfr[2][4];
            #pragma unroll
            for (int nq = 0; nq < 2; nq++)
                ldmx4(bfr[nq], sB + so + (uint32_t)((wn + nq*16 + brow) * SMROW
                                                    + s*32 + bsel));
            #pragma unroll
            for (int mt = 0; mt < 4; mt++)
                #pragma unroll
                for (int nt = 0; nt < 4; nt++)
                    mma16816(acc[mt][nt], afr[mt],
                             bfr[nt >> 1][(nt & 1) * 2],
                             bfr[nt >> 1][(nt & 1) * 2 + 1]);
        }
        __syncthreads();
        stg = (stg + 1) % 3;
    }

    // epilogue: frag layout m16n8: (c0,c1)->row g, cols 2t,2t+1; (c2,c3)->row g+8
    const int er = lane >> 2, ec = (lane & 3) * 2;
    #pragma unroll
    for (int mt = 0; mt < 4; mt++) {
        #pragma unroll
        for (int nt = 0; nt < 4; nt++) {
            const int gr = row0 + wm + mt*16 + er;
            const int gc = col0 + wn + nt*8 + ec;
            float2 v0 = make_float2(acc[mt][nt][0], acc[mt][nt][1]);
            float2 v1 = make_float2(acc[mt][nt][2], acc[mt][nt][3]);
            if (ADD_SKIP) {
                float2 s0 = *reinterpret_cast<const float2*>(skip + (size_t)gr * N + gc);
                float2 s1 = *reinterpret_cast<const float2*>(skip + (size_t)(gr+8) * N + gc);
                v0.x += s0.x; v0.y += s0.y; v1.x += s1.x; v1.y += s1.y;
            }
            *reinterpret_cast<float2*>(C + (size_t)gr * N + gc)     = v0;
            *reinterpret_cast<float2*>(C + (size_t)(gr+8) * N + gc) = v1;
        }
    }
}

// ---------------------------------------------------------------------------
// Banded attention. Grid: (L/QT, H, B), 256 threads, dynamic smem:
//   Ks[192 rows x stride 68] fp32 (K tile, reused for V), Ps[64 x 196].
// 4 threads/query (part = tid&3); part owns keys j = 4*jj + part (interleaved)
// -> the 4 partner rows are consecutive; with the 68-float row stride their
// bank starts differ by 4 words => conflict-free LDS.128 (queries broadcast).
// Epilogue writes bf16-split att [hi|hi|lo].
// ---------------------------------------------------------------------------
__global__ __launch_bounds__(256, 2) void attn_kernel(
    const float* __restrict__ qkv, __nv_bfloat16* __restrict__ attb)
{
    extern __shared__ __align__(16) float asm_[];
    float* Ks = asm_;                 // KT*KROW floats (~51 KB)
    float* Ps = asm_ + KT * KROW;     // QT*PROW floats (~49 KB)

    const int qt = blockIdx.x, h = blockIdx.y, b = blockIdx.z;
    const int q0 = qt * QT;
    const int k0 = q0 - 64;
    const int tid  = threadIdx.x;
    const int part = tid & 3;
    const int q    = tid >> 2;
    const size_t base = (size_t)b * LSEQ * QKVC;
    float* prow = &Ps[q * PROW + part * 49];   // 49: conflict-free part stride

    // ---- K tile (row stride KROW) ----
    for (int idx = tid; idx < KT * (DH/4); idx += 256) {
        const int j = idx >> 4, dc = idx & 15;
        const int kg = k0 + j;
        float4 val = make_float4(0.f, 0.f, 0.f, 0.f);
        if (kg >= 0 && kg < LSEQ)
            val = *reinterpret_cast<const float4*>(
                qkv + base + (size_t)kg * QKVC + DMODEL + h*DH + dc*4);
        *reinterpret_cast<float4*>(&Ks[j*KROW + dc*4]) = val;
    }
    __syncthreads();

    // ---- QK scores -> Ps (masked, scaled); track local max ----
    float mx = -1e30f;
    {
        float qf[DH];
        const float4* qp = reinterpret_cast<const float4*>(
            qkv + base + (size_t)(q0 + q) * QKVC + h*DH);
        #pragma unroll
        for (int dc = 0; dc < 16; dc++) {
            float4 v = qp[dc];
            qf[dc*4+0] = v.x; qf[dc*4+1] = v.y; qf[dc*4+2] = v.z; qf[dc*4+3] = v.w;
        }
        #pragma unroll 4
        for (int jj = 0; jj < 48; jj++) {
            const int j = jj * 4 + part;          // interleaved key ownership
            float s = 0.0f;
            const float4* kp = reinterpret_cast<const float4*>(&Ks[j*KROW]);
            #pragma unroll
            for (int dc = 0; dc < 16; dc++) {
                float4 kv = kp[dc];
                s += qf[dc*4+0]*kv.x + qf[dc*4+1]*kv.y
                   + qf[dc*4+2]*kv.z + qf[dc*4+3]*kv.w;
            }
            s *= 0.125f;
            const int kg = k0 + j;
            const bool valid = (j >= q) && (j <= q + 128) && (kg >= 0) && (kg < LSEQ);
            s = valid ? s : -1e30f;
            prow[jj] = s;
            mx = fmaxf(mx, s);
        }
    }
    mx = fmaxf(mx, __shfl_xor_sync(0xffffffffu, mx, 1));
    mx = fmaxf(mx, __shfl_xor_sync(0xffffffffu, mx, 2));

    // all K reads done -> safe to overwrite Ks with V
    __syncthreads();
    for (int idx = tid; idx < KT * (DH/4); idx += 256) {
        const int j = idx >> 4, dc = idx & 15;
        const int kg = k0 + j;
        float4 val = make_float4(0.f, 0.f, 0.f, 0.f);
        if (kg >= 0 && kg < LSEQ)
            val = *reinterpret_cast<const float4*>(
                qkv + base + (size_t)kg * QKVC + 2*DMODEL + h*DH + dc*4);
        *reinterpret_cast<float4*>(&Ks[j*KROW + dc*4]) = val;
    }

    // exp pass on own Ps entries (no cross-thread deps; overlaps V load)
    float sum = 0.0f;
    #pragma unroll 4
    for (int jj = 0; jj < 48; jj++) {
        const float e = __expf(prow[jj] - mx);
        prow[jj] = e;
        sum += e;
    }
    sum += __shfl_xor_sync(0xffffffffu, sum, 1);
    sum += __shfl_xor_sync(0xffffffffu, sum, 2);
    const float inv = 1.0f / sum;             // self-key always valid => sum > 0
    __syncthreads();                          // V tile complete

    // ---- PV from smem ----
    float acc[DH];
    #pragma unroll
    for (int d = 0; d < DH; d++) acc[d] = 0.0f;
    #pragma unroll 2
    for (int jj = 0; jj < 48; jj++) {
        const float pv = prow[jj];            // e (unnormalized)
        const int j = jj * 4 + part;
        const float4* vp = reinterpret_cast<const float4*>(&Ks[j*KROW]);
        #pragma unroll
        for (int dc = 0; dc < 16; dc++) {
            float4 v = vp[dc];
            acc[dc*4+0] += pv * v.x; acc[dc*4+1] += pv * v.y;
            acc[dc*4+2] += pv * v.z; acc[dc*4+3] += pv * v.w;
        }
    }
    #pragma unroll
    for (int d = 0; d < DH; d++) {
        float r = acc[d] * inv;
        r += __shfl_xor_sync(0xffffffffu, r, 1);
        r += __shfl_xor_sync(0xffffffffu, r, 2);
        acc[d] = r;
    }
    if (part == 0) {
        __nv_bfloat16* rowb = attb + ((size_t)b * LSEQ + q0 + q) * K3;
        #pragma unroll
        for (int dc = 0; dc < 16; dc++) {
            __nv_bfloat16 hh[4], ll[4];
            #pragma unroll
            for (int i = 0; i < 4; i++) {
                const float v = acc[dc*4+i];
                hh[i] = __float2bfloat16(v);
                ll[i] = __float2bfloat16(v - __bfloat162float(hh[i]));
            }
            const int c = h*DH + dc*4;
            *reinterpret_cast<uint2*>(&rowb[c])            = *reinterpret_cast<uint2*>(hh);
            *reinterpret_cast<uint2*>(&rowb[DMODEL + c])   = *reinterpret_cast<uint2*>(hh);
            *reinterpret_cast<uint2*>(&rowb[2*DMODEL + c]) = *reinterpret_cast<uint2*>(ll);
        }
    }
}

// ---------------------------------------------------------------------------
// Launch
// ---------------------------------------------------------------------------
extern "C" void kernel_launch(void* const* d_in, const int* in_sizes, int n_in,
                              void* d_out, int out_size)
{
    const float* x      = (const float*)d_in[0];
    const float* w_norm = (const float*)d_in[1];
    const float* w_qkv  = (const float*)d_in[2];
    const float* w_out  = (const float*)d_in[3];
    float* out = (float*)d_out;

    float *qkv_p;
    __nv_bfloat16 *xnb_p, *attb_p, *wqkvb_p, *woutb_p;
    cudaGetSymbolAddress((void**)&qkv_p,   g_qkv);
    cudaGetSymbolAddress((void**)&xnb_p,   g_xnb);
    cudaGetSymbolAddress((void**)&attb_p,  g_attb);
    cudaGetSymbolAddress((void**)&wqkvb_p, g_wqkvb);
    cudaGetSymbolAddress((void**)&woutb_p, g_woutb);

    // opt-in dynamic smem (host-side attribute set; graph-capture safe)
    cudaFuncSetAttribute(gemm_bf16_mma<false>,
                         cudaFuncAttributeMaxDynamicSharedMemorySize, GEMM_SMEM);
    cudaFuncSetAttribute(gemm_bf16_mma<true>,
                         cudaFuncAttributeMaxDynamicSharedMemorySize, GEMM_SMEM);
    cudaFuncSetAttribute(attn_kernel,
                         cudaFuncAttributeMaxDynamicSharedMemorySize, ATTN_SMEM);

    // 1) RMSNorm + bf16 split of activations
    rmsnorm_split_kernel<<<ROWS, 256>>>(x, w_norm, xnb_p);

    // 1b) weight splits
    split_w_kernel<<<(QKVC * DMODEL + 255) / 256, 256>>>(w_qkv, wqkvb_p, QKVC * DMODEL);
    split_w_kernel<<<(DMODEL * DMODEL + 255) / 256, 256>>>(w_out, woutb_p, DMODEL * DMODEL);

    // 2) QKV GEMM (HMMA): [4096,3072] fp32
    {
        dim3 grid(QKVC / 128, ROWS / 128);   // (24, 32)
        gemm_bf16_mma<false><<<grid, 256, GEMM_SMEM>>>(xnb_p, wqkvb_p, nullptr, qkv_p, QKVC);
    }

    // 3) Banded attention (fp32), writes bf16-split att
    {
        dim3 grid(LSEQ / QT, NHEADS, BATCH); // (32, 16, 2)
        attn_kernel<<<grid, 256, ATTN_SMEM>>>(qkv_p, attb_p);
    }

    // 4) out GEMM (HMMA) + skip: [4096,1024] fp32
    {
        dim3 grid(DMODEL / 128, ROWS / 128); // (8, 32)
        gemm_bf16_mma<true><<<grid, 256, GEMM_SMEM>>>(attb_p, woutb_p, x, out, DMODEL);
    }
}